// round 1
// baseline (speedup 1.0000x reference)
#include <cuda_runtime.h>

static constexpr int NB = 4;      // batch
static constexpr int NT = 1568;   // tokens (8*14*14 == 32*7*7)
static constexpr int NC = 512;    // channels
static constexpr int NH = 8;      // heads
static constexpr int DH = 64;     // head dim
static constexpr int NM = NB * NT; // 6272 rows

// ---------------- scratch (static device allocations; no cudaMalloc) -------
__device__ float g_t1[NB*NT*NC];
__device__ float g_t2[NB*NT*NC];
__device__ float g_ln[NB*NT*NC];
__device__ float g_q1[NB*NT*NC];
__device__ float g_k1[NB*NT*NC];
__device__ float g_v1[NB*NT*NC];
__device__ float g_q2[NB*NT*NC];
__device__ float g_k2[NB*NT*NC];
__device__ float g_v2[NB*NT*NC];

// ---------------- tokenize: x[b][c][n] -> t[b][n][c] (tiled transpose) -----
__global__ void tok_kernel(const float* __restrict__ x, float* __restrict__ t) {
    __shared__ float tile[32][33];
    int b  = blockIdx.z;
    int n0 = blockIdx.x * 32, c0 = blockIdx.y * 32;
    int nx = n0 + threadIdx.x;
    // NT = 49*32, NC = 16*32 : no bounds guards needed
    #pragma unroll
    for (int i = 0; i < 32; i += 8) {
        int c = c0 + threadIdx.y + i;
        tile[threadIdx.y + i][threadIdx.x] = x[((size_t)b*NC + c)*NT + nx];
    }
    __syncthreads();
    int cx = c0 + threadIdx.x;
    #pragma unroll
    for (int i = 0; i < 32; i += 8) {
        int n = n0 + threadIdx.y + i;
        t[((size_t)b*NT + n)*NC + cx] = tile[threadIdx.x][threadIdx.y + i];
    }
}

// ---------------- LayerNorm over last dim (512), one block per row ---------
__global__ void ln_kernel(const float* __restrict__ t, const float* __restrict__ gamma,
                          const float* __restrict__ beta, float* __restrict__ out) {
    int row = blockIdx.x;
    int tid = threadIdx.x; // 128 threads, 4 floats each
    const float4* x4 = (const float4*)(t + (size_t)row * NC);
    float4 v = x4[tid];
    float s  = v.x + v.y + v.z + v.w;
    float s2 = v.x*v.x + v.y*v.y + v.z*v.z + v.w*v.w;
    #pragma unroll
    for (int o = 16; o > 0; o >>= 1) {
        s  += __shfl_xor_sync(0xffffffffu, s,  o);
        s2 += __shfl_xor_sync(0xffffffffu, s2, o);
    }
    __shared__ float ss[4], ss2[4];
    int w = tid >> 5;
    if ((tid & 31) == 0) { ss[w] = s; ss2[w] = s2; }
    __syncthreads();
    s  = ss[0] + ss[1] + ss[2] + ss[3];
    s2 = ss2[0] + ss2[1] + ss2[2] + ss2[3];
    float mean = s * (1.0f / NC);
    float var  = s2 * (1.0f / NC) - mean * mean;
    float rstd = rsqrtf(var + 1e-5f);
    float4 g4 = ((const float4*)gamma)[tid];
    float4 b4 = ((const float4*)beta)[tid];
    float4 o4;
    o4.x = (v.x - mean) * rstd * g4.x + b4.x;
    o4.y = (v.y - mean) * rstd * g4.y + b4.y;
    o4.z = (v.z - mean) * rstd * g4.z + b4.z;
    o4.w = (v.w - mean) * rstd * g4.w + b4.w;
    ((float4*)(out + (size_t)row * NC))[tid] = o4;
}

// ---------------- GEMM: Y[m][n] = sum_k X[m][k]*W[n][k] (+ epilogue) -------
// MODE 0: Y row-major [NM][NC], epilogue = +bias
// MODE 1: output head:  z = relu(acc+bias)*rsqrt(1+eps)*bng+bnb,
//         stored transposed as Y[b][o][n] (detokenized conv output layout)
template<int MODE>
__global__ void gemm_kernel(const float* __restrict__ X, const float* __restrict__ W,
                            const float* __restrict__ bias, float* __restrict__ Y,
                            const float* __restrict__ bng, const float* __restrict__ bnb) {
    constexpr int BM = 64, BN = 64, BK = 32;
    __shared__ float As[BK][BM + 4];
    __shared__ float Bs[BK][BN + 4];
    int m0 = blockIdx.y * BM, n0 = blockIdx.x * BN;
    int tid = threadIdx.x;           // 256 threads
    int tx = tid & 15, ty = tid >> 4;
    float acc[4][4] = {};
    for (int k0 = 0; k0 < NC; k0 += BK) {
        #pragma unroll
        for (int i = tid; i < BM*BK; i += 256) {
            int m = i >> 5, k = i & 31;
            As[k][m] = X[(size_t)(m0 + m) * NC + k0 + k];
            Bs[k][m] = W[(size_t)(n0 + m) * NC + k0 + k];
        }
        __syncthreads();
        #pragma unroll
        for (int k = 0; k < BK; k++) {
            float4 a4 = *(const float4*)&As[k][ty*4];
            float4 b4 = *(const float4*)&Bs[k][tx*4];
            float av[4] = {a4.x, a4.y, a4.z, a4.w};
            float bv[4] = {b4.x, b4.y, b4.z, b4.w};
            #pragma unroll
            for (int i = 0; i < 4; i++)
                #pragma unroll
                for (int j = 0; j < 4; j++)
                    acc[i][j] += av[i] * bv[j];
        }
        __syncthreads();
    }
    if (MODE == 0) {
        #pragma unroll
        for (int i = 0; i < 4; i++) {
            int m = m0 + ty*4 + i;
            #pragma unroll
            for (int j = 0; j < 4; j++) {
                int n = n0 + tx*4 + j;
                Y[(size_t)m * NC + n] = acc[i][j] + bias[n];
            }
        }
    } else {
        const float bnscale = rsqrtf(1.0f + 1e-5f);
        #pragma unroll
        for (int i = 0; i < 4; i++) {
            int m = m0 + ty*4 + i;
            int b = m / NT, n = m % NT;
            #pragma unroll
            for (int j = 0; j < 4; j++) {
                int o = n0 + tx*4 + j;
                float z = acc[i][j] + bias[o];
                z = fmaxf(z, 0.0f) * bnscale;
                Y[((size_t)b * NC + o) * NT + n] = z * bng[o] + bnb[o];
            }
        }
    }
}

// ---------------- flash cross-attention, residual add fused ----------------
// Q,K,V: [B,NT,NC]; per (b,h) uses columns h*64..h*64+63. T += softmax(QK^T/8)V
__global__ void attn_kernel(const float* __restrict__ Q, const float* __restrict__ K,
                            const float* __restrict__ V, float* __restrict__ T) {
    constexpr int BQ = 64, BKt = 64;
    extern __shared__ float sm[];
    float* QsT = sm;                         // [DH][BQ+4]  (d-major)
    float* KsT = QsT + DH*(BQ+4);            // [DH][BKt+4]
    float* Vs  = KsT + DH*(BKt+4);           // [BKt][DH+4]
    float* Ss  = Vs  + BKt*(DH+4);           // [BQ][BKt+1]
    float* m_s = Ss  + BQ*(BKt+1);
    float* l_s = m_s + BQ;
    float* c_s = l_s + BQ;

    int q0 = blockIdx.x * BQ;
    int h  = blockIdx.y, b = blockIdx.z;
    int tid = threadIdx.x;                   // 256 threads
    int tx = tid & 15, ty = tid >> 4;
    const size_t base = ((size_t)b * NT) * NC + h * DH;

    for (int i = tid; i < BQ*DH; i += 256) {
        int r = i >> 6, d = i & 63;
        float q = (q0 + r < NT) ? Q[base + (size_t)(q0 + r)*NC + d] : 0.0f;
        QsT[d*(BQ+4) + r] = q * 0.125f;      // 1/sqrt(64)
    }
    if (tid < BQ) { m_s[tid] = -1e30f; l_s[tid] = 0.0f; }

    float acc[4][4] = {};
    for (int k0 = 0; k0 < NT; k0 += BKt) {
        __syncthreads();   // protect Ss/Vs from previous iteration (and Q load)
        for (int i = tid; i < BKt*DH; i += 256) {
            int r = i >> 6, d = i & 63;
            bool ok = (k0 + r < NT);
            size_t off = base + (size_t)(k0 + r)*NC + d;
            KsT[d*(BKt+4) + r] = ok ? K[off] : 0.0f;
            Vs[r*(DH+4) + d]   = ok ? V[off] : 0.0f;
        }
        __syncthreads();
        // S = Q K^T
        float sacc[4][4] = {};
        #pragma unroll
        for (int d = 0; d < DH; d++) {
            float4 a4 = *(const float4*)&QsT[d*(BQ+4)  + ty*4];
            float4 b4 = *(const float4*)&KsT[d*(BKt+4) + tx*4];
            float av[4] = {a4.x, a4.y, a4.z, a4.w};
            float bv[4] = {b4.x, b4.y, b4.z, b4.w};
            #pragma unroll
            for (int i = 0; i < 4; i++)
                #pragma unroll
                for (int j = 0; j < 4; j++)
                    sacc[i][j] += av[i] * bv[j];
        }
        #pragma unroll
        for (int i = 0; i < 4; i++)
            #pragma unroll
            for (int j = 0; j < 4; j++) {
                int cc = tx*4 + j;
                Ss[(ty*4+i)*(BKt+1) + cc] = (k0 + cc < NT) ? sacc[i][j] : -1e30f;
            }
        __syncthreads();
        // online softmax per row (64 rows handled by threads 0..63)
        if (tid < BQ) {
            float* row = Ss + tid*(BKt+1);
            float mold = m_s[tid];
            float mt = mold;
            #pragma unroll 8
            for (int c = 0; c < BKt; c++) mt = fmaxf(mt, row[c]);
            float corr = __expf(mold - mt);
            float sum = 0.0f;
            #pragma unroll 8
            for (int c = 0; c < BKt; c++) {
                float p = __expf(row[c] - mt);
                row[c] = p;
                sum += p;
            }
            m_s[tid] = mt;
            l_s[tid] = l_s[tid] * corr + sum;
            c_s[tid] = corr;
        }
        __syncthreads();
        // O = O*corr + P V
        float cr[4];
        #pragma unroll
        for (int i = 0; i < 4; i++) cr[i] = c_s[ty*4 + i];
        #pragma unroll
        for (int i = 0; i < 4; i++)
            #pragma unroll
            for (int j = 0; j < 4; j++) acc[i][j] *= cr[i];
        #pragma unroll
        for (int c = 0; c < BKt; c++) {
            float4 v4 = *(const float4*)&Vs[c*(DH+4) + tx*4];
            float vv[4] = {v4.x, v4.y, v4.z, v4.w};
            float pr[4];
            #pragma unroll
            for (int i = 0; i < 4; i++) pr[i] = Ss[(ty*4+i)*(BKt+1) + c];
            #pragma unroll
            for (int i = 0; i < 4; i++)
                #pragma unroll
                for (int j = 0; j < 4; j++) acc[i][j] += pr[i] * vv[j];
        }
    }
    // epilogue: residual add T += O / l
    #pragma unroll
    for (int i = 0; i < 4; i++) {
        int r = q0 + ty*4 + i;
        if (r < NT) {
            float inv = 1.0f / l_s[ty*4 + i];
            size_t off = base + (size_t)r*NC + tx*4;
            #pragma unroll
            for (int j = 0; j < 4; j++)
                T[off + j] += acc[i][j] * inv;
        }
    }
}

// ---------------------------------------------------------------------------
extern "C" void kernel_launch(void* const* d_in, const int* in_sizes, int n_in,
                              void* d_out, int out_size) {
    const float* x1    = (const float*)d_in[0];
    const float* x2    = (const float*)d_in[1];
    const float* Wq1   = (const float*)d_in[2];
    const float* bq1   = (const float*)d_in[3];
    const float* Wk1   = (const float*)d_in[4];
    const float* bk1   = (const float*)d_in[5];
    const float* Wv1   = (const float*)d_in[6];
    const float* bv1   = (const float*)d_in[7];
    const float* ln1g  = (const float*)d_in[8];
    const float* ln1b  = (const float*)d_in[9];
    const float* Wq2   = (const float*)d_in[10];
    const float* bq2   = (const float*)d_in[11];
    const float* Wk2   = (const float*)d_in[12];
    const float* bk2   = (const float*)d_in[13];
    const float* Wv2   = (const float*)d_in[14];
    const float* bv2   = (const float*)d_in[15];
    const float* ln2g  = (const float*)d_in[16];
    const float* ln2b  = (const float*)d_in[17];
    const float* o1w   = (const float*)d_in[18];
    const float* o1b   = (const float*)d_in[19];
    const float* bn1g  = (const float*)d_in[20];
    const float* bn1b  = (const float*)d_in[21];
    const float* o2w   = (const float*)d_in[22];
    const float* o2b   = (const float*)d_in[23];
    const float* bn2g  = (const float*)d_in[24];
    const float* bn2b  = (const float*)d_in[25];
    float* out = (float*)d_out;

    float *t1, *t2, *lnb, *q1, *k1, *v1, *q2, *k2, *v2;
    cudaGetSymbolAddress((void**)&t1, g_t1);
    cudaGetSymbolAddress((void**)&t2, g_t2);
    cudaGetSymbolAddress((void**)&lnb, g_ln);
    cudaGetSymbolAddress((void**)&q1, g_q1);
    cudaGetSymbolAddress((void**)&k1, g_k1);
    cudaGetSymbolAddress((void**)&v1, g_v1);
    cudaGetSymbolAddress((void**)&q2, g_q2);
    cudaGetSymbolAddress((void**)&k2, g_k2);
    cudaGetSymbolAddress((void**)&v2, g_v2);

    const int ATTN_SMEM = (DH*(64+4)*2 + 64*(DH+4) + 64*65 + 3*64) * (int)sizeof(float);
    cudaFuncSetAttribute(attn_kernel, cudaFuncAttributeMaxDynamicSharedMemorySize, ATTN_SMEM);

    dim3 tokGrid(NT/32, NC/32, NB), tokBlk(32, 8);
    tok_kernel<<<tokGrid, tokBlk>>>(x1, t1);
    tok_kernel<<<tokGrid, tokBlk>>>(x2, t2);

    dim3 gGrid(NC/64, NM/64);           // (8, 98)
    dim3 aGrid((NT + 63)/64, NH, NB);   // (25, 8, 4)

    for (int i = 0; i < 3; i++) {
        const float* wq1i = Wq1 + (size_t)i*NC*NC;  const float* bq1i = bq1 + i*NC;
        const float* wk1i = Wk1 + (size_t)i*NC*NC;  const float* bk1i = bk1 + i*NC;
        const float* wv1i = Wv1 + (size_t)i*NC*NC;  const float* bv1i = bv1 + i*NC;
        const float* wq2i = Wq2 + (size_t)i*NC*NC;  const float* bq2i = bq2 + i*NC;
        const float* wk2i = Wk2 + (size_t)i*NC*NC;  const float* bk2i = bk2 + i*NC;
        const float* wv2i = Wv2 + (size_t)i*NC*NC;  const float* bv2i = bv2 + i*NC;

        // stream 1 projections: q1 = LN(t1)Wq1^T, k1/v1 from t2
        ln_kernel<<<NM, 128>>>(t1, ln1g + i*NC, ln1b + i*NC, lnb);
        gemm_kernel<0><<<gGrid, 256>>>(lnb, wq1i, bq1i, q1, nullptr, nullptr);
        gemm_kernel<0><<<gGrid, 256>>>(t2,  wk1i, bk1i, k1, nullptr, nullptr);
        gemm_kernel<0><<<gGrid, 256>>>(t2,  wv1i, bv1i, v1, nullptr, nullptr);
        // stream 2 projections: q2 = LN(t2)Wq2^T, k2/v2 from t1 (pre-update t1)
        ln_kernel<<<NM, 128>>>(t2, ln2g + i*NC, ln2b + i*NC, lnb);
        gemm_kernel<0><<<gGrid, 256>>>(lnb, wq2i, bq2i, q2, nullptr, nullptr);
        gemm_kernel<0><<<gGrid, 256>>>(t1,  wk2i, bk2i, k2, nullptr, nullptr);
        gemm_kernel<0><<<gGrid, 256>>>(t1,  wv2i, bv2i, v2, nullptr, nullptr);
        // attention + residual
        attn_kernel<<<aGrid, 256, ATTN_SMEM>>>(q1, k1, v1, t1);
        attn_kernel<<<aGrid, 256, ATTN_SMEM>>>(q2, k2, v2, t2);
    }

    // output heads (conv1x1 + relu + bn), written in [b][o][n] layout
    gemm_kernel<1><<<gGrid, 256>>>(t1, o1w, o1b, out, bn1g, bn1b);
    gemm_kernel<1><<<gGrid, 256>>>(t2, o2w, o2b, out + (size_t)NB*NC*NT, bn2g, bn2b);
}

// round 2
// speedup vs baseline: 2.4550x; 2.4550x over previous
#include <cuda_runtime.h>
#include <cstdint>

static constexpr int NB = 4;
static constexpr int NT = 1568;
static constexpr int NC = 512;
static constexpr int NH = 8;
static constexpr int DH = 64;
static constexpr int NM = NB * NT; // 6272

// ---------------- scratch ---------------------------------------------------
__device__ float g_t1[NB*NT*NC];
__device__ float g_t2[NB*NT*NC];
__device__ float g_ln[NB*NT*NC];
__device__ float g_q1[NB*NT*NC];
__device__ float g_k1[NB*NT*NC];
__device__ float g_v1[NB*NT*NC];
__device__ float g_q2[NB*NT*NC];
__device__ float g_k2[NB*NT*NC];
__device__ float g_v2[NB*NT*NC];

// ---------------- mma helpers ----------------------------------------------
__device__ __forceinline__ uint32_t f2tf(float f) {
    uint32_t u;
    asm("cvt.rna.tf32.f32 %0, %1;\n" : "=r"(u) : "f"(f));
    return u;
}
__device__ __forceinline__ void mma_tf32(float* c, const uint32_t* a, const uint32_t* b) {
    asm volatile(
        "mma.sync.aligned.m16n8k8.row.col.f32.tf32.tf32.f32 "
        "{%0,%1,%2,%3}, {%4,%5,%6,%7}, {%8,%9}, {%0,%1,%2,%3};\n"
        : "+f"(c[0]), "+f"(c[1]), "+f"(c[2]), "+f"(c[3])
        : "r"(a[0]), "r"(a[1]), "r"(a[2]), "r"(a[3]), "r"(b[0]), "r"(b[1]));
}

// ---------------- tokenize --------------------------------------------------
__global__ void tok_kernel(const float* __restrict__ x, float* __restrict__ t) {
    __shared__ float tile[32][33];
    int b  = blockIdx.z;
    int n0 = blockIdx.x * 32, c0 = blockIdx.y * 32;
    int nx = n0 + threadIdx.x;
    #pragma unroll
    for (int i = 0; i < 32; i += 8) {
        int c = c0 + threadIdx.y + i;
        tile[threadIdx.y + i][threadIdx.x] = x[((size_t)b*NC + c)*NT + nx];
    }
    __syncthreads();
    int cx = c0 + threadIdx.x;
    #pragma unroll
    for (int i = 0; i < 32; i += 8) {
        int n = n0 + threadIdx.y + i;
        t[((size_t)b*NT + n)*NC + cx] = tile[threadIdx.x][threadIdx.y + i];
    }
}

// ---------------- LayerNorm -------------------------------------------------
__global__ void ln_kernel(const float* __restrict__ t, const float* __restrict__ gamma,
                          const float* __restrict__ beta, float* __restrict__ out) {
    int row = blockIdx.x;
    int tid = threadIdx.x; // 128
    const float4* x4 = (const float4*)(t + (size_t)row * NC);
    float4 v = x4[tid];
    float s  = v.x + v.y + v.z + v.w;
    float s2 = v.x*v.x + v.y*v.y + v.z*v.z + v.w*v.w;
    #pragma unroll
    for (int o = 16; o > 0; o >>= 1) {
        s  += __shfl_xor_sync(0xffffffffu, s,  o);
        s2 += __shfl_xor_sync(0xffffffffu, s2, o);
    }
    __shared__ float ss[4], ss2[4];
    int w = tid >> 5;
    if ((tid & 31) == 0) { ss[w] = s; ss2[w] = s2; }
    __syncthreads();
    s  = ss[0] + ss[1] + ss[2] + ss[3];
    s2 = ss2[0] + ss2[1] + ss2[2] + ss2[3];
    float mean = s * (1.0f / NC);
    float var  = s2 * (1.0f / NC) - mean * mean;
    float rstd = rsqrtf(var + 1e-5f);
    float4 g4 = ((const float4*)gamma)[tid];
    float4 b4 = ((const float4*)beta)[tid];
    float4 o4;
    o4.x = (v.x - mean) * rstd * g4.x + b4.x;
    o4.y = (v.y - mean) * rstd * g4.y + b4.y;
    o4.z = (v.z - mean) * rstd * g4.z + b4.z;
    o4.w = (v.w - mean) * rstd * g4.w + b4.w;
    ((float4*)(out + (size_t)row * NC))[tid] = o4;
}

// ---------------- TF32 tensor-core GEMM ------------------------------------
// Y[m][n] = sum_k X[m][k] * W[n][k] (+ epilogue).  M=6272, N=512, K=512.
// MODE 0: Y row-major + bias.  MODE 1: out-head (relu/bn), transposed store.
template<int MODE>
__global__ __launch_bounds__(256)
void gemm_tc(const float* __restrict__ X, const float* __restrict__ W,
             const float* __restrict__ bias, float* __restrict__ Y,
             const float* __restrict__ bng, const float* __restrict__ bnb) {
    constexpr int BM = 128, BN = 64, BK = 32, STR = 36;
    __shared__ uint32_t As[BM * STR];
    __shared__ uint32_t Bs[BN * STR];
    const int tid  = threadIdx.x;
    const int lane = tid & 31;
    const int warp = tid >> 5;
    const int g = lane >> 2, tg = lane & 3;
    const int wm = warp >> 1, wn = warp & 1;      // 4 x 2 warp grid
    const int m0 = blockIdx.y * BM, n0 = blockIdx.x * BN;

    float acc[2][4][4] = {};

    for (int k0 = 0; k0 < NC; k0 += BK) {
        // load A tile (128x32) and B tile (64x32) as tf32
        #pragma unroll
        for (int i = tid; i < BM * (BK/4); i += 256) {
            int r = i >> 3, c = (i & 7) * 4;
            float4 v = *(const float4*)&X[(size_t)(m0 + r) * NC + k0 + c];
            uint32_t* d = &As[r * STR + c];
            d[0] = f2tf(v.x); d[1] = f2tf(v.y); d[2] = f2tf(v.z); d[3] = f2tf(v.w);
        }
        #pragma unroll
        for (int i = tid; i < BN * (BK/4); i += 256) {
            int r = i >> 3, c = (i & 7) * 4;
            float4 v = *(const float4*)&W[(size_t)(n0 + r) * NC + k0 + c];
            uint32_t* d = &Bs[r * STR + c];
            d[0] = f2tf(v.x); d[1] = f2tf(v.y); d[2] = f2tf(v.z); d[3] = f2tf(v.w);
        }
        __syncthreads();
        #pragma unroll
        for (int kk = 0; kk < BK; kk += 8) {
            uint32_t a[2][4], b[4][2];
            #pragma unroll
            for (int mt = 0; mt < 2; mt++) {
                int rb = wm * 32 + mt * 16;
                a[mt][0] = As[(rb + g    ) * STR + kk + tg];
                a[mt][1] = As[(rb + g + 8) * STR + kk + tg];
                a[mt][2] = As[(rb + g    ) * STR + kk + tg + 4];
                a[mt][3] = As[(rb + g + 8) * STR + kk + tg + 4];
            }
            #pragma unroll
            for (int nt = 0; nt < 4; nt++) {
                int nb = wn * 32 + nt * 8;
                b[nt][0] = Bs[(nb + g) * STR + kk + tg];
                b[nt][1] = Bs[(nb + g) * STR + kk + tg + 4];
            }
            #pragma unroll
            for (int mt = 0; mt < 2; mt++)
                #pragma unroll
                for (int nt = 0; nt < 4; nt++)
                    mma_tf32(acc[mt][nt], a[mt], b[nt]);
        }
        __syncthreads();
    }

    #pragma unroll
    for (int mt = 0; mt < 2; mt++) {
        #pragma unroll
        for (int nt = 0; nt < 4; nt++) {
            int r0 = m0 + wm * 32 + mt * 16 + g;
            int c0 = n0 + wn * 32 + nt * 8 + 2 * tg;
            if (MODE == 0) {
                float b0 = bias[c0], b1 = bias[c0 + 1];
                Y[(size_t)r0 * NC + c0    ]      = acc[mt][nt][0] + b0;
                Y[(size_t)r0 * NC + c0 + 1]      = acc[mt][nt][1] + b1;
                Y[(size_t)(r0+8) * NC + c0    ]  = acc[mt][nt][2] + b0;
                Y[(size_t)(r0+8) * NC + c0 + 1]  = acc[mt][nt][3] + b1;
            } else {
                const float bns = rsqrtf(1.0f + 1e-5f);
                #pragma unroll
                for (int e = 0; e < 4; e++) {
                    int r = r0 + (e >> 1) * 8;
                    int o = c0 + (e & 1);
                    int b = r / NT, n = r % NT;
                    float z = acc[mt][nt][e] + bias[o];
                    z = fmaxf(z, 0.0f) * bns;
                    Y[((size_t)b * NC + o) * NT + n] = z * bng[o] + bnb[o];
                }
            }
        }
    }
}

// ---------------- FlashAttention-2 on TF32 mma ------------------------------
// Q,K,V: [B,NT,NC] fp32; per (b,h) use cols h*64..h*64+63. T += softmax(QK^T/8)V
__global__ __launch_bounds__(128)
void attn_tc(const float* __restrict__ Q, const float* __restrict__ K,
             const float* __restrict__ V, float* __restrict__ T) {
    constexpr int STR = 68;
    extern __shared__ uint32_t sm[];
    uint32_t* Qs = sm;                 // [64][STR] tf32, pre-scaled by 1/8
    uint32_t* Ks = Qs + 64 * STR;      // [64][STR] token-major
    uint32_t* Vs = Ks + 64 * STR;      // [64][STR] token-major
    uint32_t* Ps = Vs + 64 * STR;      // [64][STR] P rows (warp-private blocks)

    const int q0 = blockIdx.x * 64;
    const int h  = blockIdx.y, b = blockIdx.z;
    const int tid = threadIdx.x;
    const int lane = tid & 31, warp = tid >> 5;
    const int g = lane >> 2, tg = lane & 3;
    const int wr = warp * 16;          // this warp's Q-row base within tile
    const size_t base = ((size_t)b * NT) * NC + h * DH;

    // load Q tile (scaled)
    #pragma unroll
    for (int i = tid; i < 64 * 16; i += 128) {
        int r = i >> 4, c = (i & 15) * 4;
        uint32_t* d = &Qs[r * STR + c];
        if (q0 + r < NT) {
            float4 v = *(const float4*)&Q[base + (size_t)(q0 + r) * NC + c];
            d[0] = f2tf(v.x * 0.125f); d[1] = f2tf(v.y * 0.125f);
            d[2] = f2tf(v.z * 0.125f); d[3] = f2tf(v.w * 0.125f);
        } else {
            d[0] = 0; d[1] = 0; d[2] = 0; d[3] = 0;
        }
    }

    float o[8][4] = {};
    float mrow0 = -1e30f, mrow1 = -1e30f, lrow0 = 0.0f, lrow1 = 0.0f;

    for (int kt = 0; kt < NT; kt += 64) {
        __syncthreads();
        // load K,V tiles
        #pragma unroll
        for (int i = tid; i < 64 * 16; i += 128) {
            int r = i >> 4, c = (i & 15) * 4;
            uint32_t* dk = &Ks[r * STR + c];
            uint32_t* dv = &Vs[r * STR + c];
            if (kt + r < NT) {
                size_t off = base + (size_t)(kt + r) * NC + c;
                float4 vk = *(const float4*)&K[off];
                float4 vv = *(const float4*)&V[off];
                dk[0] = f2tf(vk.x); dk[1] = f2tf(vk.y); dk[2] = f2tf(vk.z); dk[3] = f2tf(vk.w);
                dv[0] = f2tf(vv.x); dv[1] = f2tf(vv.y); dv[2] = f2tf(vv.z); dv[3] = f2tf(vv.w);
            } else {
                dk[0]=0; dk[1]=0; dk[2]=0; dk[3]=0;
                dv[0]=0; dv[1]=0; dv[2]=0; dv[3]=0;
            }
        }
        __syncthreads();

        // S = Q K^T  (warp computes 16 x 64)
        float s[8][4] = {};
        #pragma unroll
        for (int kk = 0; kk < DH; kk += 8) {
            uint32_t a[4];
            a[0] = Qs[(wr + g    ) * STR + kk + tg];
            a[1] = Qs[(wr + g + 8) * STR + kk + tg];
            a[2] = Qs[(wr + g    ) * STR + kk + tg + 4];
            a[3] = Qs[(wr + g + 8) * STR + kk + tg + 4];
            #pragma unroll
            for (int nt = 0; nt < 8; nt++) {
                uint32_t bb[2];
                bb[0] = Ks[(nt * 8 + g) * STR + kk + tg];
                bb[1] = Ks[(nt * 8 + g) * STR + kk + tg + 4];
                mma_tf32(s[nt], a, bb);
            }
        }

        // mask tail columns
        if (kt + 64 > NT) {
            #pragma unroll
            for (int nt = 0; nt < 8; nt++) {
                int c0 = kt + nt * 8 + 2 * tg;
                if (c0     >= NT) { s[nt][0] = -1e30f; s[nt][2] = -1e30f; }
                if (c0 + 1 >= NT) { s[nt][1] = -1e30f; s[nt][3] = -1e30f; }
            }
        }

        // online softmax
        float mx0 = -1e30f, mx1 = -1e30f;
        #pragma unroll
        for (int nt = 0; nt < 8; nt++) {
            mx0 = fmaxf(mx0, fmaxf(s[nt][0], s[nt][1]));
            mx1 = fmaxf(mx1, fmaxf(s[nt][2], s[nt][3]));
        }
        mx0 = fmaxf(mx0, __shfl_xor_sync(0xffffffffu, mx0, 1));
        mx0 = fmaxf(mx0, __shfl_xor_sync(0xffffffffu, mx0, 2));
        mx1 = fmaxf(mx1, __shfl_xor_sync(0xffffffffu, mx1, 1));
        mx1 = fmaxf(mx1, __shfl_xor_sync(0xffffffffu, mx1, 2));
        float mn0 = fmaxf(mrow0, mx0), mn1 = fmaxf(mrow1, mx1);
        float cr0 = __expf(mrow0 - mn0), cr1 = __expf(mrow1 - mn1);
        mrow0 = mn0; mrow1 = mn1;

        float sum0 = 0.0f, sum1 = 0.0f;
        #pragma unroll
        for (int nt = 0; nt < 8; nt++) {
            float p0 = __expf(s[nt][0] - mn0);
            float p1 = __expf(s[nt][1] - mn0);
            float p2 = __expf(s[nt][2] - mn1);
            float p3 = __expf(s[nt][3] - mn1);
            sum0 += p0 + p1; sum1 += p2 + p3;
            int cc = nt * 8 + 2 * tg;
            Ps[(wr + g    ) * STR + cc    ] = f2tf(p0);
            Ps[(wr + g    ) * STR + cc + 1] = f2tf(p1);
            Ps[(wr + g + 8) * STR + cc    ] = f2tf(p2);
            Ps[(wr + g + 8) * STR + cc + 1] = f2tf(p3);
        }
        sum0 += __shfl_xor_sync(0xffffffffu, sum0, 1);
        sum0 += __shfl_xor_sync(0xffffffffu, sum0, 2);
        sum1 += __shfl_xor_sync(0xffffffffu, sum1, 1);
        sum1 += __shfl_xor_sync(0xffffffffu, sum1, 2);
        lrow0 = lrow0 * cr0 + sum0;
        lrow1 = lrow1 * cr1 + sum1;

        #pragma unroll
        for (int nt = 0; nt < 8; nt++) {
            o[nt][0] *= cr0; o[nt][1] *= cr0;
            o[nt][2] *= cr1; o[nt][3] *= cr1;
        }
        __syncwarp();

        // O += P V   (warp-private P rows)
        #pragma unroll
        for (int kk = 0; kk < 64; kk += 8) {
            uint32_t a[4];
            a[0] = Ps[(wr + g    ) * STR + kk + tg];
            a[1] = Ps[(wr + g + 8) * STR + kk + tg];
            a[2] = Ps[(wr + g    ) * STR + kk + tg + 4];
            a[3] = Ps[(wr + g + 8) * STR + kk + tg + 4];
            #pragma unroll
            for (int nt = 0; nt < 8; nt++) {
                uint32_t bb[2];
                bb[0] = Vs[(kk + tg    ) * STR + nt * 8 + g];
                bb[1] = Vs[(kk + tg + 4) * STR + nt * 8 + g];
                mma_tf32(o[nt], a, bb);
            }
        }
        __syncwarp();
    }

    // epilogue: residual add T += O / l
    int r0 = q0 + wr + g, r1 = r0 + 8;
    float inv0 = 1.0f / lrow0, inv1 = 1.0f / lrow1;
    #pragma unroll
    for (int nt = 0; nt < 8; nt++) {
        int d = nt * 8 + 2 * tg;
        if (r0 < NT) {
            size_t off = base + (size_t)r0 * NC + d;
            T[off]     += o[nt][0] * inv0;
            T[off + 1] += o[nt][1] * inv0;
        }
        if (r1 < NT) {
            size_t off = base + (size_t)r1 * NC + d;
            T[off]     += o[nt][2] * inv1;
            T[off + 1] += o[nt][3] * inv1;
        }
    }
}

// ---------------------------------------------------------------------------
extern "C" void kernel_launch(void* const* d_in, const int* in_sizes, int n_in,
                              void* d_out, int out_size) {
    const float* x1    = (const float*)d_in[0];
    const float* x2    = (const float*)d_in[1];
    const float* Wq1   = (const float*)d_in[2];
    const float* bq1   = (const float*)d_in[3];
    const float* Wk1   = (const float*)d_in[4];
    const float* bk1   = (const float*)d_in[5];
    const float* Wv1   = (const float*)d_in[6];
    const float* bv1   = (const float*)d_in[7];
    const float* ln1g  = (const float*)d_in[8];
    const float* ln1b  = (const float*)d_in[9];
    const float* Wq2   = (const float*)d_in[10];
    const float* bq2   = (const float*)d_in[11];
    const float* Wk2   = (const float*)d_in[12];
    const float* bk2   = (const float*)d_in[13];
    const float* Wv2   = (const float*)d_in[14];
    const float* bv2   = (const float*)d_in[15];
    const float* ln2g  = (const float*)d_in[16];
    const float* ln2b  = (const float*)d_in[17];
    const float* o1w   = (const float*)d_in[18];
    const float* o1b   = (const float*)d_in[19];
    const float* bn1g  = (const float*)d_in[20];
    const float* bn1b  = (const float*)d_in[21];
    const float* o2w   = (const float*)d_in[22];
    const float* o2b   = (const float*)d_in[23];
    const float* bn2g  = (const float*)d_in[24];
    const float* bn2b  = (const float*)d_in[25];
    float* out = (float*)d_out;

    float *t1, *t2, *lnb, *q1, *k1, *v1, *q2, *k2, *v2;
    cudaGetSymbolAddress((void**)&t1, g_t1);
    cudaGetSymbolAddress((void**)&t2, g_t2);
    cudaGetSymbolAddress((void**)&lnb, g_ln);
    cudaGetSymbolAddress((void**)&q1, g_q1);
    cudaGetSymbolAddress((void**)&k1, g_k1);
    cudaGetSymbolAddress((void**)&v1, g_v1);
    cudaGetSymbolAddress((void**)&q2, g_q2);
    cudaGetSymbolAddress((void**)&k2, g_k2);
    cudaGetSymbolAddress((void**)&v2, g_v2);

    const int ATTN_SMEM = 4 * 64 * 68 * (int)sizeof(uint32_t); // 69632 B
    cudaFuncSetAttribute(attn_tc, cudaFuncAttributeMaxDynamicSharedMemorySize, ATTN_SMEM);

    dim3 tokGrid(NT/32, NC/32, NB), tokBlk(32, 8);
    tok_kernel<<<tokGrid, tokBlk>>>(x1, t1);
    tok_kernel<<<tokGrid, tokBlk>>>(x2, t2);

    dim3 gGrid(NC/64, NM/128);          // (8, 49)
    dim3 aGrid((NT + 63)/64, NH, NB);   // (25, 8, 4)

    for (int i = 0; i < 3; i++) {
        const float* wq1i = Wq1 + (size_t)i*NC*NC;  const float* bq1i = bq1 + i*NC;
        const float* wk1i = Wk1 + (size_t)i*NC*NC;  const float* bk1i = bk1 + i*NC;
        const float* wv1i = Wv1 + (size_t)i*NC*NC;  const float* bv1i = bv1 + i*NC;
        const float* wq2i = Wq2 + (size_t)i*NC*NC;  const float* bq2i = bq2 + i*NC;
        const float* wk2i = Wk2 + (size_t)i*NC*NC;  const float* bk2i = bk2 + i*NC;
        const float* wv2i = Wv2 + (size_t)i*NC*NC;  const float* bv2i = bv2 + i*NC;

        ln_kernel<<<NM, 128>>>(t1, ln1g + i*NC, ln1b + i*NC, lnb);
        gemm_tc<0><<<gGrid, 256>>>(lnb, wq1i, bq1i, q1, nullptr, nullptr);
        gemm_tc<0><<<gGrid, 256>>>(t2,  wk1i, bk1i, k1, nullptr, nullptr);
        gemm_tc<0><<<gGrid, 256>>>(t2,  wv1i, bv1i, v1, nullptr, nullptr);
        ln_kernel<<<NM, 128>>>(t2, ln2g + i*NC, ln2b + i*NC, lnb);
        gemm_tc<0><<<gGrid, 256>>>(lnb, wq2i, bq2i, q2, nullptr, nullptr);
        gemm_tc<0><<<gGrid, 256>>>(t1,  wk2i, bk2i, k2, nullptr, nullptr);
        gemm_tc<0><<<gGrid, 256>>>(t1,  wv2i, bv2i, v2, nullptr, nullptr);
        attn_tc<<<aGrid, 128, ATTN_SMEM>>>(q1, k1, v1, t1);
        attn_tc<<<aGrid, 128, ATTN_SMEM>>>(q2, k2, v2, t2);
    }

    gemm_tc<1><<<gGrid, 256>>>(t1, o1w, o1b, out, bn1g, bn1b);
    gemm_tc<1><<<gGrid, 256>>>(t2, o2w, o2b, out + (size_t)NB*NC*NT, bn2g, bn2b);
}

// round 3
// speedup vs baseline: 3.4946x; 1.4234x over previous
#include <cuda_runtime.h>
#include <cstdint>

static constexpr int NB = 4, NT = 1568, NC = 512, NH = 8, DH = 64;
static constexpr int NM = NB * NT;   // 6272
static constexpr int N2 = NC * NC;   // 262144

// ---------------- scratch ---------------------------------------------------
__device__ float g_t1[NB*NT*NC];
__device__ float g_t2[NB*NT*NC];
__device__ float g_t1f[NB*NT*NC];
__device__ float g_t2f[NB*NT*NC];
__device__ float g_ln[NB*NT*NC];
__device__ float g_q1[NB*NT*NC];
__device__ float g_k1[NB*NT*NC];
__device__ float g_v1[NB*NT*NC];
__device__ float g_q2[NB*NT*NC];
__device__ float g_k2[NB*NT*NC];
__device__ float g_v2[NB*NT*NC];
__device__ float g_wf[20*N2];        // tf32-rounded weights

// ---------------- helpers ---------------------------------------------------
__device__ __forceinline__ uint32_t f2tf(float f) {
    uint32_t u;
    asm("cvt.rna.tf32.f32 %0, %1;\n" : "=r"(u) : "f"(f));
    return u;
}
__device__ __forceinline__ float f2tff(float f) { return __uint_as_float(f2tf(f)); }

__device__ __forceinline__ void mma_tf32(float* c, const uint32_t* a, const uint32_t* b) {
    asm volatile(
        "mma.sync.aligned.m16n8k8.row.col.f32.tf32.tf32.f32 "
        "{%0,%1,%2,%3}, {%4,%5,%6,%7}, {%8,%9}, {%0,%1,%2,%3};\n"
        : "+f"(c[0]), "+f"(c[1]), "+f"(c[2]), "+f"(c[3])
        : "r"(a[0]), "r"(a[1]), "r"(a[2]), "r"(a[3]), "r"(b[0]), "r"(b[1]));
}
__device__ __forceinline__ void cp16(uint32_t dst, const void* src) {
    asm volatile("cp.async.cg.shared.global [%0], [%1], 16;\n" :: "r"(dst), "l"(src));
}
__device__ __forceinline__ void cp16z(uint32_t dst, const void* src, int bytes) {
    asm volatile("cp.async.cg.shared.global [%0], [%1], 16, %2;\n" :: "r"(dst), "l"(src), "r"(bytes));
}
__device__ __forceinline__ void cp_commit() { asm volatile("cp.async.commit_group;\n"); }
__device__ __forceinline__ void cp_wait0()  { asm volatile("cp.async.wait_group 0;\n"); }

// ---------------- weight pre-conversion ------------------------------------
struct WPtrs { const float* p[8]; };
__global__ void wcvt_kernel(WPtrs w, float* __restrict__ dst) {
    int mat = blockIdx.y;               // 0..19
    const float* src;
    if (mat < 18) src = w.p[mat/3] + (size_t)(mat%3) * N2;
    else          src = w.p[6 + (mat - 18)];
    int i = (blockIdx.x * 256 + threadIdx.x) * 4;
    float4 v = *(const float4*)(src + i);
    float4 o;
    o.x = f2tff(v.x); o.y = f2tff(v.y); o.z = f2tff(v.z); o.w = f2tff(v.w);
    *(float4*)(dst + (size_t)mat * N2 + i) = o;
}

// ---------------- tokenize (fp32 + tf32 mirror) -----------------------------
__global__ void tok_kernel(const float* __restrict__ x, float* __restrict__ t,
                           float* __restrict__ tf) {
    __shared__ float tile[32][33];
    int b  = blockIdx.z;
    int n0 = blockIdx.x * 32, c0 = blockIdx.y * 32;
    int nx = n0 + threadIdx.x;
    #pragma unroll
    for (int i = 0; i < 32; i += 8) {
        int c = c0 + threadIdx.y + i;
        tile[threadIdx.y + i][threadIdx.x] = x[((size_t)b*NC + c)*NT + nx];
    }
    __syncthreads();
    int cx = c0 + threadIdx.x;
    #pragma unroll
    for (int i = 0; i < 32; i += 8) {
        int n = n0 + threadIdx.y + i;
        float v = tile[threadIdx.x][threadIdx.y + i];
        size_t off = ((size_t)b*NT + n)*NC + cx;
        t[off]  = v;
        tf[off] = f2tff(v);
    }
}

// ---------------- LayerNorm (fp32 in, tf32 out) -----------------------------
__global__ void ln_kernel(const float* __restrict__ t, const float* __restrict__ gamma,
                          const float* __restrict__ beta, float* __restrict__ out) {
    int row = blockIdx.x;
    int tid = threadIdx.x; // 128
    const float4* x4 = (const float4*)(t + (size_t)row * NC);
    float4 v = x4[tid];
    float s  = v.x + v.y + v.z + v.w;
    float s2 = v.x*v.x + v.y*v.y + v.z*v.z + v.w*v.w;
    #pragma unroll
    for (int o = 16; o > 0; o >>= 1) {
        s  += __shfl_xor_sync(0xffffffffu, s,  o);
        s2 += __shfl_xor_sync(0xffffffffu, s2, o);
    }
    __shared__ float ss[4], ss2[4];
    int w = tid >> 5;
    if ((tid & 31) == 0) { ss[w] = s; ss2[w] = s2; }
    __syncthreads();
    s  = ss[0] + ss[1] + ss[2] + ss[3];
    s2 = ss2[0] + ss2[1] + ss2[2] + ss2[3];
    float mean = s * (1.0f / NC);
    float var  = s2 * (1.0f / NC) - mean * mean;
    float rstd = rsqrtf(var + 1e-5f);
    float4 g4 = ((const float4*)gamma)[tid];
    float4 b4 = ((const float4*)beta)[tid];
    float4 o4;
    o4.x = f2tff((v.x - mean) * rstd * g4.x + b4.x);
    o4.y = f2tff((v.y - mean) * rstd * g4.y + b4.y);
    o4.z = f2tff((v.z - mean) * rstd * g4.z + b4.z);
    o4.w = f2tff((v.w - mean) * rstd * g4.w + b4.w);
    ((float4*)(out + (size_t)row * NC))[tid] = o4;
}

// ---------------- TF32 GEMM, cp.async double-buffered -----------------------
// Y[m][n] = sum_k X[m][k]*W[n][k].  X,W already tf32-rounded fp32 bits.
// MODE 0: Y = tf32((acc+bias)*scale)  (feeds attention mma)
// MODE 1: out-head epilogue (relu/bn), fp32 transposed store
template<int MODE>
__global__ __launch_bounds__(256)
void gemm_tc(const float* __restrict__ X, const float* __restrict__ W,
             const float* __restrict__ bias, float* __restrict__ Y, float scale,
             const float* __restrict__ bng, const float* __restrict__ bnb) {
    constexpr int BM = 128, BN = 64, BK = 32;
    extern __shared__ float smem[];
    float* As = smem;                 // [2][BM*BK]
    float* Bs = smem + 2*BM*BK;       // [2][BN*BK]
    const uint32_t sb = (uint32_t)__cvta_generic_to_shared(smem);
    const int tid = threadIdx.x, lane = tid & 31, warp = tid >> 5;
    const int g = lane >> 2, tg = lane & 3;
    const int wm = warp >> 1, wn = warp & 1;
    const int m0 = blockIdx.y * BM, n0 = blockIdx.x * BN;

    float acc[2][4][4] = {};

    // stage issue: XOR-swizzled 16B chunks
    auto issue = [&](int st, int k0) {
        uint32_t aB = sb + (uint32_t)(st*BM*BK)*4u;
        uint32_t bB = sb + (uint32_t)(2*BM*BK + st*BN*BK)*4u;
        #pragma unroll
        for (int i = 0; i < 4; i++) {
            int idx = tid + i*256;           // 0..1023
            int r = idx >> 3, c4 = idx & 7;
            cp16(aB + 4u*(r*32 + ((c4 ^ (r & 7)) << 2)),
                 X + (size_t)(m0 + r)*NC + k0 + c4*4);
        }
        #pragma unroll
        for (int i = 0; i < 2; i++) {
            int idx = tid + i*256;           // 0..511
            int r = idx >> 3, c4 = idx & 7;
            cp16(bB + 4u*(r*32 + ((c4 ^ (r & 7)) << 2)),
                 W + (size_t)(n0 + r)*NC + k0 + c4*4);
        }
        cp_commit();
    };

    issue(0, 0);
    #pragma unroll 1
    for (int it = 0; it < NC/BK; ++it) {
        cp_wait0();
        __syncthreads();
        if (it + 1 < NC/BK) issue((it + 1) & 1, (it + 1)*BK);
        const uint32_t* A = (const uint32_t*)(As + (it & 1)*BM*BK);
        const uint32_t* B = (const uint32_t*)(Bs + (it & 1)*BN*BK);
        #pragma unroll
        for (int kk = 0; kk < BK; kk += 8) {
            const int c0 = kk >> 2, c1 = c0 + 1;
            uint32_t a[2][4], b[4][2];
            #pragma unroll
            for (int mt = 0; mt < 2; mt++) {
                int r0 = wm*32 + mt*16 + g, r1 = r0 + 8;   // r&7 == g
                a[mt][0] = A[r0*32 + ((c0 ^ g) << 2) + tg];
                a[mt][1] = A[r1*32 + ((c0 ^ g) << 2) + tg];
                a[mt][2] = A[r0*32 + ((c1 ^ g) << 2) + tg];
                a[mt][3] = A[r1*32 + ((c1 ^ g) << 2) + tg];
            }
            #pragma unroll
            for (int nt = 0; nt < 4; nt++) {
                int r = wn*32 + nt*8 + g;                  // r&7 == g
                b[nt][0] = B[r*32 + ((c0 ^ g) << 2) + tg];
                b[nt][1] = B[r*32 + ((c1 ^ g) << 2) + tg];
            }
            #pragma unroll
            for (int mt = 0; mt < 2; mt++)
                #pragma unroll
                for (int nt = 0; nt < 4; nt++)
                    mma_tf32(acc[mt][nt], a[mt], b[nt]);
        }
    }

    #pragma unroll
    for (int mt = 0; mt < 2; mt++) {
        #pragma unroll
        for (int nt = 0; nt < 4; nt++) {
            int r0 = m0 + wm*32 + mt*16 + g;
            int c0 = n0 + wn*32 + nt*8 + 2*tg;
            if (MODE == 0) {
                float b0 = bias[c0], b1 = bias[c0 + 1];
                Y[(size_t)r0*NC + c0    ]     = f2tff((acc[mt][nt][0] + b0) * scale);
                Y[(size_t)r0*NC + c0 + 1]     = f2tff((acc[mt][nt][1] + b1) * scale);
                Y[(size_t)(r0+8)*NC + c0    ] = f2tff((acc[mt][nt][2] + b0) * scale);
                Y[(size_t)(r0+8)*NC + c0 + 1] = f2tff((acc[mt][nt][3] + b1) * scale);
            } else {
                const float bns = rsqrtf(1.0f + 1e-5f);
                #pragma unroll
                for (int e = 0; e < 4; e++) {
                    int r = r0 + (e >> 1)*8;
                    int o = c0 + (e & 1);
                    int b = r / NT, n = r % NT;
                    float z = acc[mt][nt][e] + bias[o];
                    z = fmaxf(z, 0.0f) * bns;
                    Y[((size_t)b*NC + o)*NT + n] = z * bng[o] + bnb[o];
                }
            }
        }
    }
}

// ---------------- FlashAttention-2, cp.async double-buffered ----------------
// Q,K,V hold tf32 bits (Q pre-scaled by 1/8).  T += softmax(QK^T)V ; Tf mirror.
__global__ __launch_bounds__(128)
void attn_tc(const float* __restrict__ Q, const float* __restrict__ K,
             const float* __restrict__ V, float* __restrict__ T,
             float* __restrict__ Tf) {
    extern __shared__ float sm[];
    float* Qs = sm;                    // [64*64]
    float* Ks = sm + 4096;             // [2][64*64]
    float* Vs = sm + 3*4096;           // [2][64*64]
    float* Ps = sm + 5*4096;           // [64*64]
    const uint32_t sb = (uint32_t)__cvta_generic_to_shared(sm);

    const int q0 = blockIdx.x * 64;
    const int h  = blockIdx.y, b = blockIdx.z;
    const int tid = threadIdx.x;
    const int lane = tid & 31, warp = tid >> 5;
    const int g = lane >> 2, tg = lane & 3;
    const int wr = warp * 16;
    const size_t base = ((size_t)b * NT) * NC + h * DH;

    // issue Q tile (group together with first KV stage)
    #pragma unroll
    for (int i = 0; i < 8; i++) {
        int idx = tid + i*128;             // 0..1023
        int r = idx >> 4, c4 = idx & 15;
        int row = q0 + r;
        int ok = (row < NT) ? 16 : 0;
        if (row >= NT) row = NT - 1;
        cp16z(sb + 4u*(r*64 + ((c4 ^ (r & 7)) << 2)),
              Q + base + (size_t)row*NC + c4*4, ok);
    }
    auto issueKV = [&](int st, int kt) {
        uint32_t kB = sb + (uint32_t)(4096 + st*4096)*4u;
        uint32_t vB = sb + (uint32_t)(3*4096 + st*4096)*4u;
        #pragma unroll
        for (int i = 0; i < 8; i++) {
            int idx = tid + i*128;
            int r = idx >> 4, c4 = idx & 15;
            int row = kt + r;
            int ok = (row < NT) ? 16 : 0;
            if (row >= NT) row = NT - 1;
            size_t off = base + (size_t)row*NC + c4*4;
            uint32_t so = 4u*(r*64 + ((c4 ^ (r & 7)) << 2));
            cp16z(kB + so, K + off, ok);
            cp16z(vB + so, V + off, ok);
        }
        cp_commit();
    };
    issueKV(0, 0);

    uint32_t qf[8][4];
    float o[8][4] = {};
    float mrow0 = -1e30f, mrow1 = -1e30f, lrow0 = 0.0f, lrow1 = 0.0f;
    constexpr int NIT = (NT + 63) / 64;   // 25

    #pragma unroll 1
    for (int it = 0; it < NIT; ++it) {
        cp_wait0();
        __syncthreads();
        if (it == 0) {
            const uint32_t* Qu = (const uint32_t*)Qs;
            #pragma unroll
            for (int ks = 0; ks < 8; ks++) {
                int c0 = ks*2, c1 = c0 + 1;
                int r0 = wr + g, r1 = r0 + 8;              // r&7 == g
                qf[ks][0] = Qu[r0*64 + ((c0 ^ g) << 2) + tg];
                qf[ks][1] = Qu[r1*64 + ((c0 ^ g) << 2) + tg];
                qf[ks][2] = Qu[r0*64 + ((c1 ^ g) << 2) + tg];
                qf[ks][3] = Qu[r1*64 + ((c1 ^ g) << 2) + tg];
            }
        }
        if (it + 1 < NIT) issueKV((it + 1) & 1, (it + 1)*64);

        const uint32_t* Ku = (const uint32_t*)(Ks + (it & 1)*4096);
        const uint32_t* Vu = (const uint32_t*)(Vs + (it & 1)*4096);
        const int kt = it * 64;

        // S = Q K^T
        float s[8][4] = {};
        #pragma unroll
        for (int ks = 0; ks < 8; ks++) {
            int c0 = ks*2, c1 = c0 + 1;
            #pragma unroll
            for (int nt = 0; nt < 8; nt++) {
                int r = nt*8 + g;                          // r&7 == g
                uint32_t bb[2];
                bb[0] = Ku[r*64 + ((c0 ^ g) << 2) + tg];
                bb[1] = Ku[r*64 + ((c1 ^ g) << 2) + tg];
                mma_tf32(s[nt], qf[ks], bb);
            }
        }

        if (kt + 64 > NT) {
            #pragma unroll
            for (int nt = 0; nt < 8; nt++) {
                int c0 = kt + nt*8 + 2*tg;
                if (c0     >= NT) { s[nt][0] = -1e30f; s[nt][2] = -1e30f; }
                if (c0 + 1 >= NT) { s[nt][1] = -1e30f; s[nt][3] = -1e30f; }
            }
        }

        // online softmax (rows g and g+8)
        float mx0 = -1e30f, mx1 = -1e30f;
        #pragma unroll
        for (int nt = 0; nt < 8; nt++) {
            mx0 = fmaxf(mx0, fmaxf(s[nt][0], s[nt][1]));
            mx1 = fmaxf(mx1, fmaxf(s[nt][2], s[nt][3]));
        }
        mx0 = fmaxf(mx0, __shfl_xor_sync(0xffffffffu, mx0, 1));
        mx0 = fmaxf(mx0, __shfl_xor_sync(0xffffffffu, mx0, 2));
        mx1 = fmaxf(mx1, __shfl_xor_sync(0xffffffffu, mx1, 1));
        mx1 = fmaxf(mx1, __shfl_xor_sync(0xffffffffu, mx1, 2));
        float mn0 = fmaxf(mrow0, mx0), mn1 = fmaxf(mrow1, mx1);
        float cr0 = __expf(mrow0 - mn0), cr1 = __expf(mrow1 - mn1);
        mrow0 = mn0; mrow1 = mn1;

        float sum0 = 0.0f, sum1 = 0.0f;
        #pragma unroll
        for (int nt = 0; nt < 8; nt++) {
            float p0 = __expf(s[nt][0] - mn0);
            float p1 = __expf(s[nt][1] - mn0);
            float p2 = __expf(s[nt][2] - mn1);
            float p3 = __expf(s[nt][3] - mn1);
            sum0 += p0 + p1; sum1 += p2 + p3;
            int cc = nt*8 + 2*tg;
            int c4 = cc >> 2, e = cc & 3;                  // e in {0,2}
            float2 w0 = make_float2(f2tff(p0), f2tff(p1));
            float2 w1 = make_float2(f2tff(p2), f2tff(p3));
            *(float2*)&Ps[(wr + g    )*64 + ((c4 ^ g) << 2) + e] = w0;
            *(float2*)&Ps[(wr + g + 8)*64 + ((c4 ^ g) << 2) + e] = w1;
        }
        sum0 += __shfl_xor_sync(0xffffffffu, sum0, 1);
        sum0 += __shfl_xor_sync(0xffffffffu, sum0, 2);
        sum1 += __shfl_xor_sync(0xffffffffu, sum1, 1);
        sum1 += __shfl_xor_sync(0xffffffffu, sum1, 2);
        lrow0 = lrow0 * cr0 + sum0;
        lrow1 = lrow1 * cr1 + sum1;

        #pragma unroll
        for (int nt = 0; nt < 8; nt++) {
            o[nt][0] *= cr0; o[nt][1] *= cr0;
            o[nt][2] *= cr1; o[nt][3] *= cr1;
        }
        __syncwarp();

        // O += P V
        const uint32_t* Pu = (const uint32_t*)Ps;
        #pragma unroll
        for (int ks = 0; ks < 8; ks++) {
            int kk = ks*8;
            int c0 = ks*2, c1 = c0 + 1;
            uint32_t a[4];
            int r0 = wr + g, r1 = r0 + 8;
            a[0] = Pu[r0*64 + ((c0 ^ g) << 2) + tg];
            a[1] = Pu[r1*64 + ((c0 ^ g) << 2) + tg];
            a[2] = Pu[r0*64 + ((c1 ^ g) << 2) + tg];
            a[3] = Pu[r1*64 + ((c1 ^ g) << 2) + tg];
            #pragma unroll
            for (int nt = 0; nt < 8; nt++) {
                int col = nt*8 + g;
                int c4 = col >> 2, e = col & 3;
                uint32_t bb[2];
                bb[0] = Vu[(kk + tg    )*64 + ((c4 ^ (tg    )) << 2) + e];
                bb[1] = Vu[(kk + tg + 4)*64 + ((c4 ^ (tg + 4)) << 2) + e];
                mma_tf32(o[nt], a, bb);
            }
        }
        __syncwarp();
    }

    // epilogue: T += O/l, tf32 mirror
    int r0 = q0 + wr + g, r1 = r0 + 8;
    float inv0 = 1.0f / lrow0, inv1 = 1.0f / lrow1;
    #pragma unroll
    for (int nt = 0; nt < 8; nt++) {
        int d = nt*8 + 2*tg;
        if (r0 < NT) {
            size_t off = base + (size_t)r0*NC + d;
            float n0 = T[off]     + o[nt][0] * inv0;
            float n1 = T[off + 1] + o[nt][1] * inv0;
            T[off] = n0;  T[off + 1] = n1;
            Tf[off] = f2tff(n0);  Tf[off + 1] = f2tff(n1);
        }
        if (r1 < NT) {
            size_t off = base + (size_t)r1*NC + d;
            float n0 = T[off]     + o[nt][2] * inv1;
            float n1 = T[off + 1] + o[nt][3] * inv1;
            T[off] = n0;  T[off + 1] = n1;
            Tf[off] = f2tff(n0);  Tf[off + 1] = f2tff(n1);
        }
    }
}

// ---------------------------------------------------------------------------
extern "C" void kernel_launch(void* const* d_in, const int* in_sizes, int n_in,
                              void* d_out, int out_size) {
    const float* x1   = (const float*)d_in[0];
    const float* x2   = (const float*)d_in[1];
    const float* Wq1  = (const float*)d_in[2];
    const float* bq1  = (const float*)d_in[3];
    const float* Wk1  = (const float*)d_in[4];
    const float* bk1  = (const float*)d_in[5];
    const float* Wv1  = (const float*)d_in[6];
    const float* bv1  = (const float*)d_in[7];
    const float* ln1g = (const float*)d_in[8];
    const float* ln1b = (const float*)d_in[9];
    const float* Wq2  = (const float*)d_in[10];
    const float* bq2  = (const float*)d_in[11];
    const float* Wk2  = (const float*)d_in[12];
    const float* bk2  = (const float*)d_in[13];
    const float* Wv2  = (const float*)d_in[14];
    const float* bv2  = (const float*)d_in[15];
    const float* ln2g = (const float*)d_in[16];
    const float* ln2b = (const float*)d_in[17];
    const float* o1w  = (const float*)d_in[18];
    const float* o1b  = (const float*)d_in[19];
    const float* bn1g = (const float*)d_in[20];
    const float* bn1b = (const float*)d_in[21];
    const float* o2w  = (const float*)d_in[22];
    const float* o2b  = (const float*)d_in[23];
    const float* bn2g = (const float*)d_in[24];
    const float* bn2b = (const float*)d_in[25];
    float* out = (float*)d_out;

    float *t1, *t2, *t1f, *t2f, *lnb, *q1, *k1, *v1, *q2, *k2, *v2, *wf;
    cudaGetSymbolAddress((void**)&t1,  g_t1);
    cudaGetSymbolAddress((void**)&t2,  g_t2);
    cudaGetSymbolAddress((void**)&t1f, g_t1f);
    cudaGetSymbolAddress((void**)&t2f, g_t2f);
    cudaGetSymbolAddress((void**)&lnb, g_ln);
    cudaGetSymbolAddress((void**)&q1,  g_q1);
    cudaGetSymbolAddress((void**)&k1,  g_k1);
    cudaGetSymbolAddress((void**)&v1,  g_v1);
    cudaGetSymbolAddress((void**)&q2,  g_q2);
    cudaGetSymbolAddress((void**)&k2,  g_k2);
    cudaGetSymbolAddress((void**)&v2,  g_v2);
    cudaGetSymbolAddress((void**)&wf,  g_wf);

    const int GEMM_SMEM = 2 * (128 + 64) * 32 * (int)sizeof(float);   // 49152
    const int ATTN_SMEM = 6 * 4096 * (int)sizeof(float);              // 98304
    cudaFuncSetAttribute(gemm_tc<0>, cudaFuncAttributeMaxDynamicSharedMemorySize, GEMM_SMEM);
    cudaFuncSetAttribute(gemm_tc<1>, cudaFuncAttributeMaxDynamicSharedMemorySize, GEMM_SMEM);
    cudaFuncSetAttribute(attn_tc,    cudaFuncAttributeMaxDynamicSharedMemorySize, ATTN_SMEM);

    // convert weights to tf32 once
    WPtrs wp;
    wp.p[0] = Wq1; wp.p[1] = Wk1; wp.p[2] = Wv1;
    wp.p[3] = Wq2; wp.p[4] = Wk2; wp.p[5] = Wv2;
    wp.p[6] = o1w; wp.p[7] = o2w;
    wcvt_kernel<<<dim3(N2/1024, 20), 256>>>(wp, wf);

    dim3 tokGrid(NT/32, NC/32, NB), tokBlk(32, 8);
    tok_kernel<<<tokGrid, tokBlk>>>(x1, t1, t1f);
    tok_kernel<<<tokGrid, tokBlk>>>(x2, t2, t2f);

    dim3 gGrid(NC/64, NM/128);          // (8, 49)
    dim3 aGrid((NT + 63)/64, NH, NB);   // (25, 8, 4)
    const float qs = 0.125f, one = 1.0f;

    for (int i = 0; i < 3; i++) {
        const float* wq1i = wf + (size_t)(0*3 + i)*N2;  const float* bq1i = bq1 + i*NC;
        const float* wk1i = wf + (size_t)(1*3 + i)*N2;  const float* bk1i = bk1 + i*NC;
        const float* wv1i = wf + (size_t)(2*3 + i)*N2;  const float* bv1i = bv1 + i*NC;
        const float* wq2i = wf + (size_t)(3*3 + i)*N2;  const float* bq2i = bq2 + i*NC;
        const float* wk2i = wf + (size_t)(4*3 + i)*N2;  const float* bk2i = bk2 + i*NC;
        const float* wv2i = wf + (size_t)(5*3 + i)*N2;  const float* bv2i = bv2 + i*NC;

        ln_kernel<<<NM, 128>>>(t1, ln1g + i*NC, ln1b + i*NC, lnb);
        gemm_tc<0><<<gGrid, 256, GEMM_SMEM>>>(lnb, wq1i, bq1i, q1, qs,  nullptr, nullptr);
        gemm_tc<0><<<gGrid, 256, GEMM_SMEM>>>(t2f, wk1i, bk1i, k1, one, nullptr, nullptr);
        gemm_tc<0><<<gGrid, 256, GEMM_SMEM>>>(t2f, wv1i, bv1i, v1, one, nullptr, nullptr);
        ln_kernel<<<NM, 128>>>(t2, ln2g + i*NC, ln2b + i*NC, lnb);
        gemm_tc<0><<<gGrid, 256, GEMM_SMEM>>>(lnb, wq2i, bq2i, q2, qs,  nullptr, nullptr);
        gemm_tc<0><<<gGrid, 256, GEMM_SMEM>>>(t1f, wk2i, bk2i, k2, one, nullptr, nullptr);
        gemm_tc<0><<<gGrid, 256, GEMM_SMEM>>>(t1f, wv2i, bv2i, v2, one, nullptr, nullptr);
        attn_tc<<<aGrid, 128, ATTN_SMEM>>>(q1, k1, v1, t1, t1f);
        attn_tc<<<aGrid, 128, ATTN_SMEM>>>(q2, k2, v2, t2, t2f);
    }

    const float* wo1 = wf + (size_t)18*N2;
    const float* wo2 = wf + (size_t)19*N2;
    gemm_tc<1><<<gGrid, 256, GEMM_SMEM>>>(t1f, wo1, o1b, out, one, bn1g, bn1b);
    gemm_tc<1><<<gGrid, 256, GEMM_SMEM>>>(t2f, wo2, o2b, out + (size_t)NB*NC*NT, one, bn2g, bn2b);
}

// round 4
// speedup vs baseline: 3.8789x; 1.1100x over previous
#include <cuda_runtime.h>
#include <cstdint>

static constexpr int NB = 4, NT = 1568, NC = 512, NH = 8, DH = 64;
static constexpr int NM = NB * NT;   // 6272
static constexpr int N2 = NC * NC;   // 262144
static constexpr float LOG2E = 1.4426950408889634f;

// ---------------- scratch ---------------------------------------------------
__device__ float g_t1[NB*NT*NC];
__device__ float g_t2[NB*NT*NC];
__device__ float g_t1f[NB*NT*NC];
__device__ float g_t2f[NB*NT*NC];
__device__ float g_ln[NB*NT*NC];
__device__ float g_q1[NB*NT*NC];
__device__ float g_k1[NB*NT*NC];
__device__ float g_v1[NB*NT*NC];
__device__ float g_q2[NB*NT*NC];
__device__ float g_k2[NB*NT*NC];
__device__ float g_v2[NB*NT*NC];
__device__ float g_vt1[NB*NT*NC];    // V transposed: [b][h][d][tok]
__device__ float g_vt2[NB*NT*NC];
__device__ float g_wf[20*N2];        // tf32-rounded weights

// ---------------- helpers ---------------------------------------------------
__device__ __forceinline__ uint32_t f2tf(float f) {
    uint32_t u;
    asm("cvt.rna.tf32.f32 %0, %1;\n" : "=r"(u) : "f"(f));
    return u;
}
__device__ __forceinline__ float f2tff(float f) { return __uint_as_float(f2tf(f)); }

__device__ __forceinline__ void mma_tf32(float* c, const uint32_t* a, const uint32_t* b) {
    asm volatile(
        "mma.sync.aligned.m16n8k8.row.col.f32.tf32.tf32.f32 "
        "{%0,%1,%2,%3}, {%4,%5,%6,%7}, {%8,%9}, {%0,%1,%2,%3};\n"
        : "+f"(c[0]), "+f"(c[1]), "+f"(c[2]), "+f"(c[3])
        : "r"(a[0]), "r"(a[1]), "r"(a[2]), "r"(a[3]), "r"(b[0]), "r"(b[1]));
}
__device__ __forceinline__ void ldsm4(uint32_t& r0, uint32_t& r1, uint32_t& r2, uint32_t& r3,
                                      uint32_t addr) {
    asm volatile("ldmatrix.sync.aligned.m8n8.x4.shared.b16 {%0,%1,%2,%3}, [%4];\n"
                 : "=r"(r0), "=r"(r1), "=r"(r2), "=r"(r3) : "r"(addr));
}
__device__ __forceinline__ void cp16(uint32_t dst, const void* src) {
    asm volatile("cp.async.cg.shared.global [%0], [%1], 16;\n" :: "r"(dst), "l"(src));
}
__device__ __forceinline__ void cp16z(uint32_t dst, const void* src, int bytes) {
    asm volatile("cp.async.cg.shared.global [%0], [%1], 16, %2;\n" :: "r"(dst), "l"(src), "r"(bytes));
}
__device__ __forceinline__ void cp_commit() { asm volatile("cp.async.commit_group;\n"); }
__device__ __forceinline__ void cp_wait0()  { asm volatile("cp.async.wait_group 0;\n"); }

// ---------------- weight pre-conversion ------------------------------------
struct WPtrs { const float* p[8]; };
__global__ void wcvt_kernel(WPtrs w, float* __restrict__ dst) {
    int mat = blockIdx.y;               // 0..19
    const float* src;
    if (mat < 18) src = w.p[mat/3] + (size_t)(mat%3) * N2;
    else          src = w.p[6 + (mat - 18)];
    int i = (blockIdx.x * 256 + threadIdx.x) * 4;
    float4 v = *(const float4*)(src + i);
    float4 o;
    o.x = f2tff(v.x); o.y = f2tff(v.y); o.z = f2tff(v.z); o.w = f2tff(v.w);
    *(float4*)(dst + (size_t)mat * N2 + i) = o;
}

// ---------------- tokenize (fp32 + tf32 mirror) -----------------------------
__global__ void tok_kernel(const float* __restrict__ x, float* __restrict__ t,
                           float* __restrict__ tf) {
    __shared__ float tile[32][33];
    int b  = blockIdx.z;
    int n0 = blockIdx.x * 32, c0 = blockIdx.y * 32;
    int nx = n0 + threadIdx.x;
    #pragma unroll
    for (int i = 0; i < 32; i += 8) {
        int c = c0 + threadIdx.y + i;
        tile[threadIdx.y + i][threadIdx.x] = x[((size_t)b*NC + c)*NT + nx];
    }
    __syncthreads();
    int cx = c0 + threadIdx.x;
    #pragma unroll
    for (int i = 0; i < 32; i += 8) {
        int n = n0 + threadIdx.y + i;
        float v = tile[threadIdx.x][threadIdx.y + i];
        size_t off = ((size_t)b*NT + n)*NC + cx;
        t[off]  = v;
        tf[off] = f2tff(v);
    }
}

// ---------------- V transpose: [b][tok][c] -> [b][h][d][tok] ----------------
__global__ void vt_kernel(const float* __restrict__ v, float* __restrict__ vt) {
    __shared__ float tile[32][33];
    int b  = blockIdx.z;
    int n0 = blockIdx.x * 32, c0 = blockIdx.y * 32;
    #pragma unroll
    for (int i = 0; i < 32; i += 8) {
        int n = n0 + threadIdx.y + i;
        tile[threadIdx.y + i][threadIdx.x] = v[((size_t)b*NT + n)*NC + c0 + threadIdx.x];
    }
    __syncthreads();
    #pragma unroll
    for (int i = 0; i < 32; i += 8) {
        int c = c0 + threadIdx.y + i;          // channel
        int h = c >> 6, d = c & 63;
        vt[(((size_t)b*NH + h)*DH + d)*NT + n0 + threadIdx.x] = tile[threadIdx.x][threadIdx.y + i];
    }
}

// ---------------- LayerNorm (fp32 in, tf32 out) -----------------------------
__global__ void ln_kernel(const float* __restrict__ t, const float* __restrict__ gamma,
                          const float* __restrict__ beta, float* __restrict__ out) {
    int row = blockIdx.x;
    int tid = threadIdx.x; // 128
    const float4* x4 = (const float4*)(t + (size_t)row * NC);
    float4 v = x4[tid];
    float s  = v.x + v.y + v.z + v.w;
    float s2 = v.x*v.x + v.y*v.y + v.z*v.z + v.w*v.w;
    #pragma unroll
    for (int o = 16; o > 0; o >>= 1) {
        s  += __shfl_xor_sync(0xffffffffu, s,  o);
        s2 += __shfl_xor_sync(0xffffffffu, s2, o);
    }
    __shared__ float ss[4], ss2[4];
    int w = tid >> 5;
    if ((tid & 31) == 0) { ss[w] = s; ss2[w] = s2; }
    __syncthreads();
    s  = ss[0] + ss[1] + ss[2] + ss[3];
    s2 = ss2[0] + ss2[1] + ss2[2] + ss2[3];
    float mean = s * (1.0f / NC);
    float var  = s2 * (1.0f / NC) - mean * mean;
    float rstd = rsqrtf(var + 1e-5f);
    float4 g4 = ((const float4*)gamma)[tid];
    float4 b4 = ((const float4*)beta)[tid];
    float4 o4;
    o4.x = f2tff((v.x - mean) * rstd * g4.x + b4.x);
    o4.y = f2tff((v.y - mean) * rstd * g4.y + b4.y);
    o4.z = f2tff((v.z - mean) * rstd * g4.z + b4.z);
    o4.w = f2tff((v.w - mean) * rstd * g4.w + b4.w);
    ((float4*)(out + (size_t)row * NC))[tid] = o4;
}

// ---------------- TF32 GEMM, cp.async + ldmatrix ----------------------------
template<int MODE>
__global__ __launch_bounds__(256)
void gemm_tc(const float* __restrict__ X, const float* __restrict__ W,
             const float* __restrict__ bias, float* __restrict__ Y, float scale,
             const float* __restrict__ bng, const float* __restrict__ bnb) {
    constexpr int BM = 128, BN = 64, BK = 32;
    extern __shared__ float smem[];
    const uint32_t sb = (uint32_t)__cvta_generic_to_shared(smem);
    const int tid = threadIdx.x, lane = tid & 31, warp = tid >> 5;
    const int g = lane >> 2, tg = lane & 3;
    const int wm = warp >> 1, wn = warp & 1;
    const int m0 = blockIdx.y * BM, n0 = blockIdx.x * BN;

    float acc[2][4][4] = {};

    auto issue = [&](int st, int k0) {
        uint32_t aB = sb + (uint32_t)(st*BM*BK)*4u;
        uint32_t bB = sb + (uint32_t)(2*BM*BK + st*BN*BK)*4u;
        #pragma unroll
        for (int i = 0; i < 4; i++) {
            int idx = tid + i*256;
            int r = idx >> 3, c4 = idx & 7;
            cp16(aB + 4u*(r*32 + ((c4 ^ (r & 7)) << 2)),
                 X + (size_t)(m0 + r)*NC + k0 + c4*4);
        }
        #pragma unroll
        for (int i = 0; i < 2; i++) {
            int idx = tid + i*256;
            int r = idx >> 3, c4 = idx & 7;
            cp16(bB + 4u*(r*32 + ((c4 ^ (r & 7)) << 2)),
                 W + (size_t)(n0 + r)*NC + k0 + c4*4);
        }
        cp_commit();
    };

    issue(0, 0);
    #pragma unroll 1
    for (int it = 0; it < NC/BK; ++it) {
        cp_wait0();
        __syncthreads();
        if (it + 1 < NC/BK) issue((it + 1) & 1, (it + 1)*BK);
        const uint32_t aBase = sb + (uint32_t)((it & 1)*BM*BK)*4u;
        const uint32_t bBase = sb + (uint32_t)(2*BM*BK + (it & 1)*BN*BK)*4u;
        #pragma unroll
        for (int kk = 0; kk < BK; kk += 8) {
            const int c0 = kk >> 2;
            uint32_t a[2][4], b[4][2];
            #pragma unroll
            for (int mt = 0; mt < 2; mt++) {
                int row = wm*32 + mt*16 + (lane & 15);
                int c4  = c0 + (lane >> 4);
                ldsm4(a[mt][0], a[mt][1], a[mt][2], a[mt][3],
                      aBase + 4u*(row*32 + ((c4 ^ (row & 7)) << 2)));
            }
            #pragma unroll
            for (int p = 0; p < 2; p++) {
                int row = wn*32 + ((p*2 + ((lane >> 4) & 1)) << 3) + (lane & 7);
                int c4  = c0 + ((lane >> 3) & 1);
                ldsm4(b[p*2][0], b[p*2][1], b[p*2+1][0], b[p*2+1][1],
                      bBase + 4u*(row*32 + ((c4 ^ (row & 7)) << 2)));
            }
            #pragma unroll
            for (int mt = 0; mt < 2; mt++)
                #pragma unroll
                for (int nt = 0; nt < 4; nt++)
                    mma_tf32(acc[mt][nt], a[mt], b[nt]);
        }
    }

    #pragma unroll
    for (int mt = 0; mt < 2; mt++) {
        #pragma unroll
        for (int nt = 0; nt < 4; nt++) {
            int r0 = m0 + wm*32 + mt*16 + g;
            int c0 = n0 + wn*32 + nt*8 + 2*tg;
            if (MODE == 0) {
                float b0 = bias[c0], b1 = bias[c0 + 1];
                Y[(size_t)r0*NC + c0    ]     = f2tff((acc[mt][nt][0] + b0) * scale);
                Y[(size_t)r0*NC + c0 + 1]     = f2tff((acc[mt][nt][1] + b1) * scale);
                Y[(size_t)(r0+8)*NC + c0    ] = f2tff((acc[mt][nt][2] + b0) * scale);
                Y[(size_t)(r0+8)*NC + c0 + 1] = f2tff((acc[mt][nt][3] + b1) * scale);
            } else {
                const float bns = rsqrtf(1.0f + 1e-5f);
                #pragma unroll
                for (int e = 0; e < 4; e++) {
                    int r = r0 + (e >> 1)*8;
                    int o = c0 + (e & 1);
                    int b = r / NT, n = r % NT;
                    float z = acc[mt][nt][e] + bias[o];
                    z = fmaxf(z, 0.0f) * bns;
                    Y[((size_t)b*NC + o)*NT + n] = z * bng[o] + bnb[o];
                }
            }
        }
    }
}

// ---------------- FlashAttention-2, ldmatrix + BQ=128 -----------------------
// Q holds tf32 bits pre-scaled by (1/8)*log2(e); scores fed to exp2.
// K: [b][tok][c] tf32.  Vt: [b][h][d][tok] tf32.  T += softmax(S)V, Tf mirror.
__global__ __launch_bounds__(256)
void attn_tc(const float* __restrict__ Q, const float* __restrict__ K,
             const float* __restrict__ Vt, float* __restrict__ T,
             float* __restrict__ Tf) {
    // smem (floats): Qs[128*64] | Ks[2][64*64] | Vs[2][64*64] | Ps[128*64]
    extern __shared__ float sm[];
    const uint32_t sb = (uint32_t)__cvta_generic_to_shared(sm);
    const uint32_t sbQ = sb;
    const uint32_t sbK0 = sb + 8192u*4u;
    const uint32_t sbV0 = sb + 16384u*4u;
    const uint32_t sbP  = sb + 24576u*4u;

    const int q0 = blockIdx.x * 128;
    const int h  = blockIdx.y, b = blockIdx.z;
    const int tid = threadIdx.x;                 // 256
    const int lane = tid & 31, warp = tid >> 5;  // 8 warps
    const int g = lane >> 2, tg = lane & 3;
    const int wr = warp * 16;
    const size_t base  = ((size_t)b * NT) * NC + h * DH;
    const size_t vbase = (((size_t)b * NH + h) * DH) * NT;

    // issue Q tile (128 rows x 64)
    #pragma unroll
    for (int i = 0; i < 8; i++) {
        int idx = tid + i*256;                   // 0..2047
        int r = idx >> 4, c4 = idx & 15;
        int row = q0 + r;
        int ok = (row < NT) ? 16 : 0;
        if (row >= NT) row = NT - 1;
        cp16z(sbQ + 4u*(r*64 + ((c4 ^ (r & 7)) << 2)),
              Q + base + (size_t)row*NC + c4*4, ok);
    }
    auto issueKV = [&](int st, int kt) {
        uint32_t kB = sbK0 + (uint32_t)(st*4096)*4u;
        uint32_t vB = sbV0 + (uint32_t)(st*4096)*4u;
        #pragma unroll
        for (int i = 0; i < 4; i++) {
            int idx = tid + i*256;               // 0..1023
            int r = idx >> 4, c4 = idx & 15;
            uint32_t so = 4u*(r*64 + ((c4 ^ (r & 7)) << 2));
            // K: row = token kt+r
            int krow = kt + r;
            int kok = (krow < NT) ? 16 : 0;
            if (krow >= NT) krow = NT - 1;
            cp16z(kB + so, K + base + (size_t)krow*NC + c4*4, kok);
            // V^T: row = dim r, cols = tokens kt + c4*4 ..
            int vtok = kt + c4*4;
            int vok = (vtok < NT) ? 16 : 0;
            if (vtok >= NT) vtok = NT - 4;
            cp16z(vB + so, Vt + vbase + (size_t)r*NT + vtok, vok);
        }
        cp_commit();
    };
    issueKV(0, 0);

    uint32_t qf[8][4];
    float o[8][4] = {};
    float mrow0 = -1e30f, mrow1 = -1e30f, lrow0 = 0.0f, lrow1 = 0.0f;
    constexpr int NIT = (NT + 63) / 64;          // 25

    #pragma unroll 1
    for (int it = 0; it < NIT; ++it) {
        cp_wait0();
        __syncthreads();
        if (it == 0) {
            #pragma unroll
            for (int ks = 0; ks < 8; ks++) {
                int row = wr + (lane & 15);
                int c4  = ks*2 + (lane >> 4);
                ldsm4(qf[ks][0], qf[ks][1], qf[ks][2], qf[ks][3],
                      sbQ + 4u*(row*64 + ((c4 ^ (row & 7)) << 2)));
            }
        }
        if (it + 1 < NIT) issueKV((it + 1) & 1, (it + 1)*64);

        const uint32_t kB = sbK0 + (uint32_t)((it & 1)*4096)*4u;
        const uint32_t vB = sbV0 + (uint32_t)((it & 1)*4096)*4u;
        const int kt = it * 64;

        // ---- S = Q K^T
        float s[8][4] = {};
        #pragma unroll
        for (int ks = 0; ks < 8; ks++) {
            int c0 = ks*2;
            #pragma unroll
            for (int p = 0; p < 4; p++) {
                int row = ((p*2 + ((lane >> 4) & 1)) << 3) + (lane & 7);
                int c4  = c0 + ((lane >> 3) & 1);
                uint32_t b0, b1, b2, b3;
                ldsm4(b0, b1, b2, b3, kB + 4u*(row*64 + ((c4 ^ (row & 7)) << 2)));
                uint32_t f0[2] = {b0, b1}, f1[2] = {b2, b3};
                mma_tf32(s[p*2    ], qf[ks], f0);
                mma_tf32(s[p*2 + 1], qf[ks], f1);
            }
        }

        if (kt + 64 > NT) {
            #pragma unroll
            for (int nt = 0; nt < 8; nt++) {
                int c0 = kt + nt*8 + 2*tg;
                if (c0     >= NT) { s[nt][0] = -1e30f; s[nt][2] = -1e30f; }
                if (c0 + 1 >= NT) { s[nt][1] = -1e30f; s[nt][3] = -1e30f; }
            }
        }

        // ---- online softmax (rows g, g+8), base-2 domain
        float mx0 = -1e30f, mx1 = -1e30f;
        #pragma unroll
        for (int nt = 0; nt < 8; nt++) {
            mx0 = fmaxf(mx0, fmaxf(s[nt][0], s[nt][1]));
            mx1 = fmaxf(mx1, fmaxf(s[nt][2], s[nt][3]));
        }
        mx0 = fmaxf(mx0, __shfl_xor_sync(0xffffffffu, mx0, 1));
        mx0 = fmaxf(mx0, __shfl_xor_sync(0xffffffffu, mx0, 2));
        mx1 = fmaxf(mx1, __shfl_xor_sync(0xffffffffu, mx1, 1));
        mx1 = fmaxf(mx1, __shfl_xor_sync(0xffffffffu, mx1, 2));
        float mn0 = fmaxf(mrow0, mx0), mn1 = fmaxf(mrow1, mx1);
        float cr0 = exp2f(mrow0 - mn0), cr1 = exp2f(mrow1 - mn1);
        mrow0 = mn0; mrow1 = mn1;

        float sum0 = 0.0f, sum1 = 0.0f;
        #pragma unroll
        for (int nt = 0; nt < 8; nt++) {
            float p0 = exp2f(s[nt][0] - mn0);
            float p1 = exp2f(s[nt][1] - mn0);
            float p2 = exp2f(s[nt][2] - mn1);
            float p3 = exp2f(s[nt][3] - mn1);
            sum0 += p0 + p1; sum1 += p2 + p3;
            int cc = nt*8 + 2*tg;
            int c4 = cc >> 2, e = cc & 3;
            float2 w0 = make_float2(f2tff(p0), f2tff(p1));
            float2 w1 = make_float2(f2tff(p2), f2tff(p3));
            *(float2*)((char*)sm + (sbP - sb) + 4u*((wr + g    )*64 + ((c4 ^ g) << 2) + e)) = w0;
            *(float2*)((char*)sm + (sbP - sb) + 4u*((wr + g + 8)*64 + ((c4 ^ g) << 2) + e)) = w1;
        }
        sum0 += __shfl_xor_sync(0xffffffffu, sum0, 1);
        sum0 += __shfl_xor_sync(0xffffffffu, sum0, 2);
        sum1 += __shfl_xor_sync(0xffffffffu, sum1, 1);
        sum1 += __shfl_xor_sync(0xffffffffu, sum1, 2);
        lrow0 = lrow0 * cr0 + sum0;
        lrow1 = lrow1 * cr1 + sum1;

        #pragma unroll
        for (int nt = 0; nt < 8; nt++) {
            o[nt][0] *= cr0; o[nt][1] *= cr0;
            o[nt][2] *= cr1; o[nt][3] *= cr1;
        }
        __syncwarp();

        // ---- O += P V   (P a-frags and V^T b-frags via ldmatrix)
        #pragma unroll
        for (int ks = 0; ks < 8; ks++) {
            int c0 = ks*2;
            uint32_t a[4];
            {
                int row = wr + (lane & 15);
                int c4  = c0 + (lane >> 4);
                ldsm4(a[0], a[1], a[2], a[3],
                      sbP + 4u*(row*64 + ((c4 ^ (row & 7)) << 2)));
            }
            #pragma unroll
            for (int p = 0; p < 4; p++) {
                int row = ((p*2 + ((lane >> 4) & 1)) << 3) + (lane & 7);  // dim
                int c4  = c0 + ((lane >> 3) & 1);                          // token chunk
                uint32_t b0, b1, b2, b3;
                ldsm4(b0, b1, b2, b3, vB + 4u*(row*64 + ((c4 ^ (row & 7)) << 2)));
                uint32_t f0[2] = {b0, b1}, f1[2] = {b2, b3};
                mma_tf32(o[p*2    ], a, f0);
                mma_tf32(o[p*2 + 1], a, f1);
            }
        }
        __syncwarp();
    }

    // epilogue: T += O/l, tf32 mirror
    int r0 = q0 + wr + g, r1 = r0 + 8;
    float inv0 = 1.0f / lrow0, inv1 = 1.0f / lrow1;
    #pragma unroll
    for (int nt = 0; nt < 8; nt++) {
        int d = nt*8 + 2*tg;
        if (r0 < NT) {
            size_t off = base + (size_t)r0*NC + d;
            float n0 = T[off]     + o[nt][0] * inv0;
            float n1 = T[off + 1] + o[nt][1] * inv0;
            T[off] = n0;  T[off + 1] = n1;
            Tf[off] = f2tff(n0);  Tf[off + 1] = f2tff(n1);
        }
        if (r1 < NT) {
            size_t off = base + (size_t)r1*NC + d;
            float n0 = T[off]     + o[nt][2] * inv1;
            float n1 = T[off + 1] + o[nt][3] * inv1;
            T[off] = n0;  T[off + 1] = n1;
            Tf[off] = f2tff(n0);  Tf[off + 1] = f2tff(n1);
        }
    }
}

// ---------------------------------------------------------------------------
extern "C" void kernel_launch(void* const* d_in, const int* in_sizes, int n_in,
                              void* d_out, int out_size) {
    const float* x1   = (const float*)d_in[0];
    const float* x2   = (const float*)d_in[1];
    const float* Wq1  = (const float*)d_in[2];
    const float* bq1  = (const float*)d_in[3];
    const float* Wk1  = (const float*)d_in[4];
    const float* bk1  = (const float*)d_in[5];
    const float* Wv1  = (const float*)d_in[6];
    const float* bv1  = (const float*)d_in[7];
    const float* ln1g = (const float*)d_in[8];
    const float* ln1b = (const float*)d_in[9];
    const float* Wq2  = (const float*)d_in[10];
    const float* bq2  = (const float*)d_in[11];
    const float* Wk2  = (const float*)d_in[12];
    const float* bk2  = (const float*)d_in[13];
    const float* Wv2  = (const float*)d_in[14];
    const float* bv2  = (const float*)d_in[15];
    const float* ln2g = (const float*)d_in[16];
    const float* ln2b = (const float*)d_in[17];
    const float* o1w  = (const float*)d_in[18];
    const float* o1b  = (const float*)d_in[19];
    const float* bn1g = (const float*)d_in[20];
    const float* bn1b = (const float*)d_in[21];
    const float* o2w  = (const float*)d_in[22];
    const float* o2b  = (const float*)d_in[23];
    const float* bn2g = (const float*)d_in[24];
    const float* bn2b = (const float*)d_in[25];
    float* out = (float*)d_out;

    float *t1, *t2, *t1f, *t2f, *lnb, *q1, *k1, *v1, *q2, *k2, *v2, *vt1, *vt2, *wf;
    cudaGetSymbolAddress((void**)&t1,  g_t1);
    cudaGetSymbolAddress((void**)&t2,  g_t2);
    cudaGetSymbolAddress((void**)&t1f, g_t1f);
    cudaGetSymbolAddress((void**)&t2f, g_t2f);
    cudaGetSymbolAddress((void**)&lnb, g_ln);
    cudaGetSymbolAddress((void**)&q1,  g_q1);
    cudaGetSymbolAddress((void**)&k1,  g_k1);
    cudaGetSymbolAddress((void**)&v1,  g_v1);
    cudaGetSymbolAddress((void**)&q2,  g_q2);
    cudaGetSymbolAddress((void**)&k2,  g_k2);
    cudaGetSymbolAddress((void**)&v2,  g_v2);
    cudaGetSymbolAddress((void**)&vt1, g_vt1);
    cudaGetSymbolAddress((void**)&vt2, g_vt2);
    cudaGetSymbolAddress((void**)&wf,  g_wf);

    const int GEMM_SMEM = 2 * (128 + 64) * 32 * (int)sizeof(float);   // 49152
    const int ATTN_SMEM = 32768 * (int)sizeof(float);                 // 131072
    cudaFuncSetAttribute(gemm_tc<0>, cudaFuncAttributeMaxDynamicSharedMemorySize, GEMM_SMEM);
    cudaFuncSetAttribute(gemm_tc<1>, cudaFuncAttributeMaxDynamicSharedMemorySize, GEMM_SMEM);
    cudaFuncSetAttribute(attn_tc,    cudaFuncAttributeMaxDynamicSharedMemorySize, ATTN_SMEM);

    WPtrs wp;
    wp.p[0] = Wq1; wp.p[1] = Wk1; wp.p[2] = Wv1;
    wp.p[3] = Wq2; wp.p[4] = Wk2; wp.p[5] = Wv2;
    wp.p[6] = o1w; wp.p[7] = o2w;
    wcvt_kernel<<<dim3(N2/1024, 20), 256>>>(wp, wf);

    dim3 tokGrid(NT/32, NC/32, NB), tokBlk(32, 8);
    tok_kernel<<<tokGrid, tokBlk>>>(x1, t1, t1f);
    tok_kernel<<<tokGrid, tokBlk>>>(x2, t2, t2f);

    dim3 gGrid(NC/64, NM/128);              // (8, 49)
    dim3 aGrid((NT + 127)/128, NH, NB);     // (13, 8, 4)
    const float qs = 0.125f * LOG2E, one = 1.0f;

    for (int i = 0; i < 3; i++) {
        const float* wq1i = wf + (size_t)(0*3 + i)*N2;  const float* bq1i = bq1 + i*NC;
        const float* wk1i = wf + (size_t)(1*3 + i)*N2;  const float* bk1i = bk1 + i*NC;
        const float* wv1i = wf + (size_t)(2*3 + i)*N2;  const float* bv1i = bv1 + i*NC;
        const float* wq2i = wf + (size_t)(3*3 + i)*N2;  const float* bq2i = bq2 + i*NC;
        const float* wk2i = wf + (size_t)(4*3 + i)*N2;  const float* bk2i = bk2 + i*NC;
        const float* wv2i = wf + (size_t)(5*3 + i)*N2;  const float* bv2i = bv2 + i*NC;

        ln_kernel<<<NM, 128>>>(t1, ln1g + i*NC, ln1b + i*NC, lnb);
        gemm_tc<0><<<gGrid, 256, GEMM_SMEM>>>(lnb, wq1i, bq1i, q1, qs,  nullptr, nullptr);
        gemm_tc<0><<<gGrid, 256, GEMM_SMEM>>>(t2f, wk1i, bk1i, k1, one, nullptr, nullptr);
        gemm_tc<0><<<gGrid, 256, GEMM_SMEM>>>(t2f, wv1i, bv1i, v1, one, nullptr, nullptr);
        vt_kernel<<<tokGrid, tokBlk>>>(v1, vt1);
        ln_kernel<<<NM, 128>>>(t2, ln2g + i*NC, ln2b + i*NC, lnb);
        gemm_tc<0><<<gGrid, 256, GEMM_SMEM>>>(lnb, wq2i, bq2i, q2, qs,  nullptr, nullptr);
        gemm_tc<0><<<gGrid, 256, GEMM_SMEM>>>(t1f, wk2i, bk2i, k2, one, nullptr, nullptr);
        gemm_tc<0><<<gGrid, 256, GEMM_SMEM>>>(t1f, wv2i, bv2i, v2, one, nullptr, nullptr);
        vt_kernel<<<tokGrid, tokBlk>>>(v2, vt2);
        attn_tc<<<aGrid, 256, ATTN_SMEM>>>(q1, k1, vt1, t1, t1f);
        attn_tc<<<aGrid, 256, ATTN_SMEM>>>(q2, k2, vt2, t2, t2f);
    }

    const float* wo1 = wf + (size_t)18*N2;
    const float* wo2 = wf + (size_t)19*N2;
    gemm_tc<1><<<gGrid, 256, GEMM_SMEM>>>(t1f, wo1, o1b, out, one, bn1g, bn1b);
    gemm_tc<1><<<gGrid, 256, GEMM_SMEM>>>(t2f, wo2, o2b, out + (size_t)NB*NC*NT, one, bn2g, bn2b);
}

// round 5
// speedup vs baseline: 7.6196x; 1.9644x over previous
#include <cuda_runtime.h>
#include <cuda_bf16.h>
#include <cstdint>

static constexpr int NB = 4, NT = 1568, NC = 512, NH = 8, DH = 64;
static constexpr int NM = NB * NT;   // 6272
static constexpr int N2 = NC * NC;   // 262144
static constexpr float LOG2E = 1.4426950408889634f;

// ---------------- scratch (float-typed for 16B alignment) -------------------
__device__ float g_t1 [NB*NT*NC];
__device__ float g_t2 [NB*NT*NC];
__device__ float g_t1f[NB*NT*NC];          // tf32 mirror for out-head
__device__ float g_t2f[NB*NT*NC];
__device__ float g_th1[NB*NT*NC/2];        // bf16 mirror of t1
__device__ float g_th2[NB*NT*NC/2];
__device__ float g_lnh[NB*NT*NC/2];        // bf16 LN output
__device__ float g_q1h[NB*NT*NC/2];
__device__ float g_k1h[NB*NT*NC/2];
__device__ float g_v1h[NB*NT*NC/2];        // V^T bf16: [b][c][tok]
__device__ float g_q2h[NB*NT*NC/2];
__device__ float g_k2h[NB*NT*NC/2];
__device__ float g_v2h[NB*NT*NC/2];
__device__ float g_wh [18*N2/2];           // bf16 proj weights
__device__ float g_wf [2*N2];              // tf32 out-head weights

// ---------------- helpers ---------------------------------------------------
__device__ __forceinline__ uint32_t f2tf(float f) {
    uint32_t u;
    asm("cvt.rna.tf32.f32 %0, %1;\n" : "=r"(u) : "f"(f));
    return u;
}
__device__ __forceinline__ float f2tff(float f) { return __uint_as_float(f2tf(f)); }

__device__ __forceinline__ void mma_bf16(float* c, const uint32_t* a, const uint32_t* b) {
    asm volatile(
        "mma.sync.aligned.m16n8k16.row.col.f32.bf16.bf16.f32 "
        "{%0,%1,%2,%3}, {%4,%5,%6,%7}, {%8,%9}, {%0,%1,%2,%3};\n"
        : "+f"(c[0]), "+f"(c[1]), "+f"(c[2]), "+f"(c[3])
        : "r"(a[0]), "r"(a[1]), "r"(a[2]), "r"(a[3]), "r"(b[0]), "r"(b[1]));
}
__device__ __forceinline__ void mma_tf32(float* c, const uint32_t* a, const uint32_t* b) {
    asm volatile(
        "mma.sync.aligned.m16n8k8.row.col.f32.tf32.tf32.f32 "
        "{%0,%1,%2,%3}, {%4,%5,%6,%7}, {%8,%9}, {%0,%1,%2,%3};\n"
        : "+f"(c[0]), "+f"(c[1]), "+f"(c[2]), "+f"(c[3])
        : "r"(a[0]), "r"(a[1]), "r"(a[2]), "r"(a[3]), "r"(b[0]), "r"(b[1]));
}
__device__ __forceinline__ void ldsm4(uint32_t& r0, uint32_t& r1, uint32_t& r2, uint32_t& r3,
                                      uint32_t addr) {
    asm volatile("ldmatrix.sync.aligned.m8n8.x4.shared.b16 {%0,%1,%2,%3}, [%4];\n"
                 : "=r"(r0), "=r"(r1), "=r"(r2), "=r"(r3) : "r"(addr));
}
__device__ __forceinline__ uint32_t packbf(float lo, float hi) {
    uint32_t d;
    asm("cvt.rn.bf16x2.f32 %0, %1, %2;\n" : "=r"(d) : "f"(hi), "f"(lo));
    return d;
}
__device__ __forceinline__ void cp16(uint32_t dst, const void* src) {
    asm volatile("cp.async.cg.shared.global [%0], [%1], 16;\n" :: "r"(dst), "l"(src));
}
__device__ __forceinline__ void cp16z(uint32_t dst, const void* src, int bytes) {
    asm volatile("cp.async.cg.shared.global [%0], [%1], 16, %2;\n" :: "r"(dst), "l"(src), "r"(bytes));
}
__device__ __forceinline__ void cp_commit() { asm volatile("cp.async.commit_group;\n"); }
__device__ __forceinline__ void cp_wait0()  { asm volatile("cp.async.wait_group 0;\n"); }

// swizzled 16B-chunk address: 8 chunks (128B) per logical row
__device__ __forceinline__ uint32_t swz(uint32_t base, int row, int c) {
    return base + (uint32_t)((row * 8 + (c ^ (row & 7))) << 4);
}

// ---------------- weight pre-conversion ------------------------------------
struct WPtrs { const float* p[8]; };
__global__ void wcvt_kernel(WPtrs w, __nv_bfloat16* __restrict__ dh, float* __restrict__ df) {
    int mat = blockIdx.y;               // 0..19
    const float* src;
    if (mat < 18) src = w.p[mat/3] + (size_t)(mat%3) * N2;
    else          src = w.p[6 + (mat - 18)];
    int i = (blockIdx.x * 256 + threadIdx.x) * 4;
    float4 v = *(const float4*)(src + i);
    if (mat < 18) {
        __nv_bfloat162* d = (__nv_bfloat162*)(dh + (size_t)mat * N2 + i);
        d[0] = __floats2bfloat162_rn(v.x, v.y);
        d[1] = __floats2bfloat162_rn(v.z, v.w);
    } else {
        float4 o;
        o.x = f2tff(v.x); o.y = f2tff(v.y); o.z = f2tff(v.z); o.w = f2tff(v.w);
        *(float4*)(df + (size_t)(mat - 18) * N2 + i) = o;
    }
}

// ---------------- tokenize (fp32 + bf16 mirror) -----------------------------
__global__ void tok_kernel(const float* __restrict__ x, float* __restrict__ t,
                           __nv_bfloat16* __restrict__ th) {
    __shared__ float tile[32][33];
    int b  = blockIdx.z;
    int n0 = blockIdx.x * 32, c0 = blockIdx.y * 32;
    int nx = n0 + threadIdx.x;
    #pragma unroll
    for (int i = 0; i < 32; i += 8) {
        int c = c0 + threadIdx.y + i;
        tile[threadIdx.y + i][threadIdx.x] = x[((size_t)b*NC + c)*NT + nx];
    }
    __syncthreads();
    int cx = c0 + threadIdx.x;
    #pragma unroll
    for (int i = 0; i < 32; i += 8) {
        int n = n0 + threadIdx.y + i;
        float v = tile[threadIdx.x][threadIdx.y + i];
        size_t off = ((size_t)b*NT + n)*NC + cx;
        t[off]  = v;
        th[off] = __float2bfloat16_rn(v);
    }
}

// ---------------- LayerNorm (fp32 in, bf16 out) -----------------------------
__global__ void ln_kernel(const float* __restrict__ t, const float* __restrict__ gamma,
                          const float* __restrict__ beta, __nv_bfloat16* __restrict__ out) {
    int row = blockIdx.x;
    int tid = threadIdx.x; // 128
    const float4* x4 = (const float4*)(t + (size_t)row * NC);
    float4 v = x4[tid];
    float s  = v.x + v.y + v.z + v.w;
    float s2 = v.x*v.x + v.y*v.y + v.z*v.z + v.w*v.w;
    #pragma unroll
    for (int o = 16; o > 0; o >>= 1) {
        s  += __shfl_xor_sync(0xffffffffu, s,  o);
        s2 += __shfl_xor_sync(0xffffffffu, s2, o);
    }
    __shared__ float ss[4], ss2[4];
    int w = tid >> 5;
    if ((tid & 31) == 0) { ss[w] = s; ss2[w] = s2; }
    __syncthreads();
    s  = ss[0] + ss[1] + ss[2] + ss[3];
    s2 = ss2[0] + ss2[1] + ss2[2] + ss2[3];
    float mean = s * (1.0f / NC);
    float var  = s2 * (1.0f / NC) - mean * mean;
    float rstd = rsqrtf(var + 1e-5f);
    float4 g4 = ((const float4*)gamma)[tid];
    float4 b4 = ((const float4*)beta)[tid];
    __nv_bfloat162* o2 = (__nv_bfloat162*)(out + (size_t)row * NC);
    o2[tid*2    ] = __floats2bfloat162_rn((v.x - mean)*rstd*g4.x + b4.x,
                                          (v.y - mean)*rstd*g4.y + b4.y);
    o2[tid*2 + 1] = __floats2bfloat162_rn((v.z - mean)*rstd*g4.z + b4.z,
                                          (v.w - mean)*rstd*g4.w + b4.w);
}

// ---------------- bf16 GEMM, cp.async + ldmatrix ----------------------------
// Y[m][n] = sum_k X[m][k]*W[n][k].  MODE 0: bf16 row-major out, (acc+bias)*scale
// MODE 1: V^T store — Y[b][n][tok] bf16 (acc+bias)
template<int MODE>
__global__ __launch_bounds__(256)
void gemm_bf(const __nv_bfloat16* __restrict__ X, const __nv_bfloat16* __restrict__ W,
             const float* __restrict__ bias, __nv_bfloat16* __restrict__ Y, float scale) {
    constexpr int BM = 128, BN = 64, BK = 64;
    extern __shared__ char smc[];
    const uint32_t sb = (uint32_t)__cvta_generic_to_shared(smc);
    // layout: A[2][128*8 chunks] @0/16384, B[2][64*8] @32768/40960
    const int tid = threadIdx.x, lane = tid & 31, warp = tid >> 5;
    const int g = lane >> 2, tg = lane & 3;
    const int wm = warp >> 1, wn = warp & 1;
    const int m0 = blockIdx.y * BM, n0 = blockIdx.x * BN;

    float acc[2][4][4] = {};

    auto issue = [&](int st, int k0) {
        uint32_t aB = sb + (uint32_t)st * 16384u;
        uint32_t bB = sb + 32768u + (uint32_t)st * 8192u;
        #pragma unroll
        for (int i = 0; i < 4; i++) {
            int idx = tid + i*256;               // 0..1023
            int r = idx >> 3, c = idx & 7;
            cp16(swz(aB, r, c), X + (size_t)(m0 + r)*NC + k0 + c*8);
        }
        #pragma unroll
        for (int i = 0; i < 2; i++) {
            int idx = tid + i*256;               // 0..511
            int r = idx >> 3, c = idx & 7;
            cp16(swz(bB, r, c), W + (size_t)(n0 + r)*NC + k0 + c*8);
        }
        cp_commit();
    };

    issue(0, 0);
    #pragma unroll 1
    for (int it = 0; it < NC/BK; ++it) {         // 8 iters
        cp_wait0();
        __syncthreads();
        if (it + 1 < NC/BK) issue((it + 1) & 1, (it + 1)*BK);
        uint32_t aB = sb + (uint32_t)(it & 1) * 16384u;
        uint32_t bB = sb + 32768u + (uint32_t)(it & 1) * 8192u;
        #pragma unroll
        for (int j = 0; j < 4; j++) {            // k16 chunks
            uint32_t a[2][4], bf[4][2];
            #pragma unroll
            for (int mt = 0; mt < 2; mt++) {
                int row = wm*32 + mt*16 + (lane & 15);
                int c   = 2*j + (lane >> 4);
                ldsm4(a[mt][0], a[mt][1], a[mt][2], a[mt][3], swz(aB, row, c));
            }
            #pragma unroll
            for (int q = 0; q < 2; q++) {
                int row = wn*32 + q*16 + ((lane >> 4) << 3) + (lane & 7);
                int c   = 2*j + ((lane >> 3) & 1);
                uint32_t r0, r1, r2, r3;
                ldsm4(r0, r1, r2, r3, swz(bB, row, c));
                bf[q*2][0] = r0; bf[q*2][1] = r1;
                bf[q*2+1][0] = r2; bf[q*2+1][1] = r3;
            }
            #pragma unroll
            for (int mt = 0; mt < 2; mt++)
                #pragma unroll
                for (int nt = 0; nt < 4; nt++)
                    mma_bf16(acc[mt][nt], a[mt], bf[nt]);
        }
    }

    #pragma unroll
    for (int mt = 0; mt < 2; mt++) {
        #pragma unroll
        for (int nt = 0; nt < 4; nt++) {
            int r0 = m0 + wm*32 + mt*16 + g;
            int c0 = n0 + wn*32 + nt*8 + 2*tg;
            if (MODE == 0) {
                float b0 = bias[c0], b1 = bias[c0 + 1];
                *(__nv_bfloat162*)(Y + (size_t)r0*NC + c0) =
                    __floats2bfloat162_rn((acc[mt][nt][0] + b0)*scale, (acc[mt][nt][1] + b1)*scale);
                *(__nv_bfloat162*)(Y + (size_t)(r0+8)*NC + c0) =
                    __floats2bfloat162_rn((acc[mt][nt][2] + b0)*scale, (acc[mt][nt][3] + b1)*scale);
            } else {
                #pragma unroll
                for (int e = 0; e < 4; e++) {
                    int r = r0 + (e >> 1)*8;
                    int o = c0 + (e & 1);
                    int b = r / NT, n = r % NT;
                    Y[((size_t)b*NC + o)*NT + n] = __float2bfloat16_rn(acc[mt][nt][e] + bias[o]);
                }
            }
        }
    }
}

// ---------------- FlashAttention-2, bf16 m16n8k16 ---------------------------
// Q pre-scaled by (1/8)*log2(e).  K: [b][tok][c].  Vt: [b][c][tok].
// T += softmax(S)V ; optional bf16 mirror Th, optional tf32 mirror Tf.
__global__ __launch_bounds__(256, 2)
void attn_bf(const __nv_bfloat16* __restrict__ Q, const __nv_bfloat16* __restrict__ K,
             const __nv_bfloat16* __restrict__ Vt, float* __restrict__ T,
             __nv_bfloat16* __restrict__ Th, float* __restrict__ Tf) {
    extern __shared__ char smc[];
    const uint32_t sb  = (uint32_t)__cvta_generic_to_shared(smc);
    const uint32_t sbQ = sb;                       // 128 rows
    // K stages @16384 + st*8192, V stages @32768 + st*8192 (64 rows each)
    const int q0 = blockIdx.x * 128;
    const int h  = blockIdx.y, b = blockIdx.z;
    const int tid = threadIdx.x;                   // 256
    const int lane = tid & 31, warp = tid >> 5;    // 8 warps x 16 q-rows
    const int g = lane >> 2, tg = lane & 3;
    const int wr = warp * 16;
    const size_t base  = ((size_t)b * NT) * NC + h * DH;
    const size_t vbase = ((size_t)b * NC + h * DH) * NT;

    // issue Q tile (joins first KV commit group)
    #pragma unroll
    for (int i = 0; i < 4; i++) {
        int idx = tid + i*256;                     // 0..1023
        int r = idx >> 3, c = idx & 7;
        int row = q0 + r;
        int ok = (row < NT) ? 16 : 0;
        if (row >= NT) row = NT - 1;
        cp16z(swz(sbQ, r, c), Q + base + (size_t)row*NC + c*8, ok);
    }
    auto issueKV = [&](int st, int kt) {
        uint32_t kB = sb + 16384u + (uint32_t)st*8192u;
        uint32_t vB = sb + 32768u + (uint32_t)st*8192u;
        #pragma unroll
        for (int i = 0; i < 2; i++) {
            int idx = tid + i*256;                 // 0..511
            int r = idx >> 3, c = idx & 7;
            int krow = kt + r;
            int kok = (krow < NT) ? 16 : 0;
            if (krow >= NT) krow = NT - 1;
            cp16z(swz(kB, r, c), K + base + (size_t)krow*NC + c*8, kok);
            int vtok = kt + c*8;
            int vok = (vtok < NT) ? 16 : 0;
            if (vtok >= NT) vtok = NT - 8;
            cp16z(swz(vB, r, c), Vt + vbase + (size_t)r*NT + vtok, vok);
        }
        cp_commit();
    };
    issueKV(0, 0);

    uint32_t qf[4][4];
    float o[8][4] = {};
    float mrow0 = -1e30f, mrow1 = -1e30f, lrow0 = 0.0f, lrow1 = 0.0f;
    constexpr int NIT = (NT + 63) / 64;            // 25

    #pragma unroll 1
    for (int it = 0; it < NIT; ++it) {
        cp_wait0();
        __syncthreads();
        if (it == 0) {
            #pragma unroll
            for (int j = 0; j < 4; j++) {
                int row = wr + (lane & 15);
                int c   = 2*j + (lane >> 4);
                ldsm4(qf[j][0], qf[j][1], qf[j][2], qf[j][3], swz(sbQ, row, c));
            }
        }
        if (it + 1 < NIT) issueKV((it + 1) & 1, (it + 1)*64);

        const uint32_t kB = sb + 16384u + (uint32_t)((it & 1))*8192u;
        const uint32_t vB = sb + 32768u + (uint32_t)((it & 1))*8192u;
        const int kt = it * 64;

        // ---- S = Q K^T  (8 token-tiles of n8)
        float s[8][4] = {};
        #pragma unroll
        for (int j = 0; j < 4; j++) {
            #pragma unroll
            for (int q = 0; q < 4; q++) {
                int row = q*16 + ((lane >> 4) << 3) + (lane & 7);
                int c   = 2*j + ((lane >> 3) & 1);
                uint32_t r0, r1, r2, r3;
                ldsm4(r0, r1, r2, r3, swz(kB, row, c));
                uint32_t f0[2] = {r0, r1}, f1[2] = {r2, r3};
                mma_bf16(s[q*2    ], qf[j], f0);
                mma_bf16(s[q*2 + 1], qf[j], f1);
            }
        }

        if (kt + 64 > NT) {
            #pragma unroll
            for (int nt = 0; nt < 8; nt++) {
                int c0 = kt + nt*8 + 2*tg;
                if (c0     >= NT) { s[nt][0] = -1e30f; s[nt][2] = -1e30f; }
                if (c0 + 1 >= NT) { s[nt][1] = -1e30f; s[nt][3] = -1e30f; }
            }
        }

        // ---- online softmax (rows g, g+8), base-2
        float mx0 = -1e30f, mx1 = -1e30f;
        #pragma unroll
        for (int nt = 0; nt < 8; nt++) {
            mx0 = fmaxf(mx0, fmaxf(s[nt][0], s[nt][1]));
            mx1 = fmaxf(mx1, fmaxf(s[nt][2], s[nt][3]));
        }
        mx0 = fmaxf(mx0, __shfl_xor_sync(0xffffffffu, mx0, 1));
        mx0 = fmaxf(mx0, __shfl_xor_sync(0xffffffffu, mx0, 2));
        mx1 = fmaxf(mx1, __shfl_xor_sync(0xffffffffu, mx1, 1));
        mx1 = fmaxf(mx1, __shfl_xor_sync(0xffffffffu, mx1, 2));
        float mn0 = fmaxf(mrow0, mx0), mn1 = fmaxf(mrow1, mx1);
        float cr0 = exp2f(mrow0 - mn0), cr1 = exp2f(mrow1 - mn1);
        mrow0 = mn0; mrow1 = mn1;

        float sum0 = 0.0f, sum1 = 0.0f;
        #pragma unroll
        for (int nt = 0; nt < 8; nt++) {
            s[nt][0] = exp2f(s[nt][0] - mn0);
            s[nt][1] = exp2f(s[nt][1] - mn0);
            s[nt][2] = exp2f(s[nt][2] - mn1);
            s[nt][3] = exp2f(s[nt][3] - mn1);
            sum0 += s[nt][0] + s[nt][1];
            sum1 += s[nt][2] + s[nt][3];
        }
        sum0 += __shfl_xor_sync(0xffffffffu, sum0, 1);
        sum0 += __shfl_xor_sync(0xffffffffu, sum0, 2);
        sum1 += __shfl_xor_sync(0xffffffffu, sum1, 1);
        sum1 += __shfl_xor_sync(0xffffffffu, sum1, 2);
        lrow0 = lrow0 * cr0 + sum0;
        lrow1 = lrow1 * cr1 + sum1;

        #pragma unroll
        for (int nt = 0; nt < 8; nt++) {
            o[nt][0] *= cr0; o[nt][1] *= cr0;
            o[nt][2] *= cr1; o[nt][3] *= cr1;
        }

        // ---- O += P V : P a-frags straight from registers (no smem roundtrip)
        #pragma unroll
        for (int j = 0; j < 4; j++) {              // token k16 chunks
            uint32_t a[4];
            a[0] = packbf(s[2*j][0],     s[2*j][1]);
            a[1] = packbf(s[2*j][2],     s[2*j][3]);
            a[2] = packbf(s[2*j + 1][0], s[2*j + 1][1]);
            a[3] = packbf(s[2*j + 1][2], s[2*j + 1][3]);
            #pragma unroll
            for (int q = 0; q < 4; q++) {          // dim-tile pairs
                int row = q*16 + ((lane >> 4) << 3) + (lane & 7);   // dim
                int c   = 2*j + ((lane >> 3) & 1);                  // token chunk
                uint32_t r0, r1, r2, r3;
                ldsm4(r0, r1, r2, r3, swz(vB, row, c));
                uint32_t f0[2] = {r0, r1}, f1[2] = {r2, r3};
                mma_bf16(o[q*2    ], a, f0);
                mma_bf16(o[q*2 + 1], a, f1);
            }
        }
    }

    // epilogue: T += O/l ; optional mirrors
    int r0 = q0 + wr + g, r1 = r0 + 8;
    float inv0 = 1.0f / lrow0, inv1 = 1.0f / lrow1;
    #pragma unroll
    for (int nt = 0; nt < 8; nt++) {
        int d = nt*8 + 2*tg;
        if (r0 < NT) {
            size_t off = base + (size_t)r0*NC + d;
            float n0 = T[off]     + o[nt][0] * inv0;
            float n1 = T[off + 1] + o[nt][1] * inv0;
            T[off] = n0;  T[off + 1] = n1;
            if (Th) *(__nv_bfloat162*)(Th + off) = __floats2bfloat162_rn(n0, n1);
            if (Tf) { Tf[off] = f2tff(n0); Tf[off + 1] = f2tff(n1); }
        }
        if (r1 < NT) {
            size_t off = base + (size_t)r1*NC + d;
            float n0 = T[off]     + o[nt][2] * inv1;
            float n1 = T[off + 1] + o[nt][3] * inv1;
            T[off] = n0;  T[off + 1] = n1;
            if (Th) *(__nv_bfloat162*)(Th + off) = __floats2bfloat162_rn(n0, n1);
            if (Tf) { Tf[off] = f2tff(n0); Tf[off + 1] = f2tff(n1); }
        }
    }
}

// ---------------- TF32 out-head GEMM (relu/bn, transposed store) ------------
__global__ __launch_bounds__(256)
void gemm_out(const float* __restrict__ X, const float* __restrict__ W,
              const float* __restrict__ bias, float* __restrict__ Y,
              const float* __restrict__ bng, const float* __restrict__ bnb) {
    constexpr int BM = 128, BN = 64, BK = 32;
    extern __shared__ float smem[];
    const uint32_t sb = (uint32_t)__cvta_generic_to_shared(smem);
    const int tid = threadIdx.x, lane = tid & 31, warp = tid >> 5;
    const int g = lane >> 2, tg = lane & 3;
    const int wm = warp >> 1, wn = warp & 1;
    const int m0 = blockIdx.y * BM, n0 = blockIdx.x * BN;

    float acc[2][4][4] = {};

    auto issue = [&](int st, int k0) {
        uint32_t aB = sb + (uint32_t)(st*BM*BK)*4u;
        uint32_t bB = sb + (uint32_t)(2*BM*BK + st*BN*BK)*4u;
        #pragma unroll
        for (int i = 0; i < 4; i++) {
            int idx = tid + i*256;
            int r = idx >> 3, c4 = idx & 7;
            cp16(aB + 4u*(r*32 + ((c4 ^ (r & 7)) << 2)),
                 X + (size_t)(m0 + r)*NC + k0 + c4*4);
        }
        #pragma unroll
        for (int i = 0; i < 2; i++) {
            int idx = tid + i*256;
            int r = idx >> 3, c4 = idx & 7;
            cp16(bB + 4u*(r*32 + ((c4 ^ (r & 7)) << 2)),
                 W + (size_t)(n0 + r)*NC + k0 + c4*4);
        }
        cp_commit();
    };

    issue(0, 0);
    #pragma unroll 1
    for (int it = 0; it < NC/BK; ++it) {
        cp_wait0();
        __syncthreads();
        if (it + 1 < NC/BK) issue((it + 1) & 1, (it + 1)*BK);
        const uint32_t aBase = sb + (uint32_t)((it & 1)*BM*BK)*4u;
        const uint32_t bBase = sb + (uint32_t)(2*BM*BK + (it & 1)*BN*BK)*4u;
        #pragma unroll
        for (int kk = 0; kk < BK; kk += 8) {
            const int c0 = kk >> 2;
            uint32_t a[2][4], b[4][2];
            #pragma unroll
            for (int mt = 0; mt < 2; mt++) {
                int row = wm*32 + mt*16 + (lane & 15);
                int c4  = c0 + (lane >> 4);
                ldsm4(a[mt][0], a[mt][1], a[mt][2], a[mt][3],
                      aBase + 4u*(row*32 + ((c4 ^ (row & 7)) << 2)));
            }
            #pragma unroll
            for (int p = 0; p < 2; p++) {
                int row = wn*32 + ((p*2 + ((lane >> 4) & 1)) << 3) + (lane & 7);
                int c4  = c0 + ((lane >> 3) & 1);
                ldsm4(b[p*2][0], b[p*2][1], b[p*2+1][0], b[p*2+1][1],
                      bBase + 4u*(row*32 + ((c4 ^ (row & 7)) << 2)));
            }
            #pragma unroll
            for (int mt = 0; mt < 2; mt++)
                #pragma unroll
                for (int nt = 0; nt < 4; nt++)
                    mma_tf32(acc[mt][nt], a[mt], b[nt]);
        }
    }

    const float bns = rsqrtf(1.0f + 1e-5f);
    #pragma unroll
    for (int mt = 0; mt < 2; mt++) {
        #pragma unroll
        for (int nt = 0; nt < 4; nt++) {
            int r0 = m0 + wm*32 + mt*16 + g;
            int c0 = n0 + wn*32 + nt*8 + 2*tg;
            #pragma unroll
            for (int e = 0; e < 4; e++) {
                int r = r0 + (e >> 1)*8;
                int o = c0 + (e & 1);
                int b = r / NT, n = r % NT;
                float z = acc[mt][nt][e] + bias[o];
                z = fmaxf(z, 0.0f) * bns;
                Y[((size_t)b*NC + o)*NT + n] = z * bng[o] + bnb[o];
            }
        }
    }
}

// ---------------------------------------------------------------------------
extern "C" void kernel_launch(void* const* d_in, const int* in_sizes, int n_in,
                              void* d_out, int out_size) {
    const float* x1   = (const float*)d_in[0];
    const float* x2   = (const float*)d_in[1];
    const float* Wq1  = (const float*)d_in[2];
    const float* bq1  = (const float*)d_in[3];
    const float* Wk1  = (const float*)d_in[4];
    const float* bk1  = (const float*)d_in[5];
    const float* Wv1  = (const float*)d_in[6];
    const float* bv1  = (const float*)d_in[7];
    const float* ln1g = (const float*)d_in[8];
    const float* ln1b = (const float*)d_in[9];
    const float* Wq2  = (const float*)d_in[10];
    const float* bq2  = (const float*)d_in[11];
    const float* Wk2  = (const float*)d_in[12];
    const float* bk2  = (const float*)d_in[13];
    const float* Wv2  = (const float*)d_in[14];
    const float* bv2  = (const float*)d_in[15];
    const float* ln2g = (const float*)d_in[16];
    const float* ln2b = (const float*)d_in[17];
    const float* o1w  = (const float*)d_in[18];
    const float* o1b  = (const float*)d_in[19];
    const float* bn1g = (const float*)d_in[20];
    const float* bn1b = (const float*)d_in[21];
    const float* o2w  = (const float*)d_in[22];
    const float* o2b  = (const float*)d_in[23];
    const float* bn2g = (const float*)d_in[24];
    const float* bn2b = (const float*)d_in[25];
    float* out = (float*)d_out;

    float *t1, *t2, *t1f, *t2f, *wf;
    void *th1, *th2, *lnh, *q1h, *k1h, *v1h, *q2h, *k2h, *v2h, *wh;
    cudaGetSymbolAddress((void**)&t1,  g_t1);
    cudaGetSymbolAddress((void**)&t2,  g_t2);
    cudaGetSymbolAddress((void**)&t1f, g_t1f);
    cudaGetSymbolAddress((void**)&t2f, g_t2f);
    cudaGetSymbolAddress(&th1, g_th1);
    cudaGetSymbolAddress(&th2, g_th2);
    cudaGetSymbolAddress(&lnh, g_lnh);
    cudaGetSymbolAddress(&q1h, g_q1h);
    cudaGetSymbolAddress(&k1h, g_k1h);
    cudaGetSymbolAddress(&v1h, g_v1h);
    cudaGetSymbolAddress(&q2h, g_q2h);
    cudaGetSymbolAddress(&k2h, g_k2h);
    cudaGetSymbolAddress(&v2h, g_v2h);
    cudaGetSymbolAddress(&wh,  g_wh);
    cudaGetSymbolAddress((void**)&wf, g_wf);
    __nv_bfloat16 *TH1 = (__nv_bfloat16*)th1, *TH2 = (__nv_bfloat16*)th2;
    __nv_bfloat16 *LNH = (__nv_bfloat16*)lnh, *WH = (__nv_bfloat16*)wh;
    __nv_bfloat16 *Q1 = (__nv_bfloat16*)q1h, *K1 = (__nv_bfloat16*)k1h, *V1 = (__nv_bfloat16*)v1h;
    __nv_bfloat16 *Q2 = (__nv_bfloat16*)q2h, *K2 = (__nv_bfloat16*)k2h, *V2 = (__nv_bfloat16*)v2h;

    const int BF_SMEM   = 49152;
    const int OUT_SMEM  = 2 * (128 + 64) * 32 * (int)sizeof(float);   // 49152
    const int ATTN_SMEM = 49152;
    cudaFuncSetAttribute(gemm_bf<0>, cudaFuncAttributeMaxDynamicSharedMemorySize, BF_SMEM);
    cudaFuncSetAttribute(gemm_bf<1>, cudaFuncAttributeMaxDynamicSharedMemorySize, BF_SMEM);
    cudaFuncSetAttribute(gemm_out,   cudaFuncAttributeMaxDynamicSharedMemorySize, OUT_SMEM);
    cudaFuncSetAttribute(attn_bf,    cudaFuncAttributeMaxDynamicSharedMemorySize, ATTN_SMEM);

    WPtrs wp;
    wp.p[0] = Wq1; wp.p[1] = Wk1; wp.p[2] = Wv1;
    wp.p[3] = Wq2; wp.p[4] = Wk2; wp.p[5] = Wv2;
    wp.p[6] = o1w; wp.p[7] = o2w;
    wcvt_kernel<<<dim3(N2/1024, 20), 256>>>(wp, WH, wf);

    dim3 tokGrid(NT/32, NC/32, NB), tokBlk(32, 8);
    tok_kernel<<<tokGrid, tokBlk>>>(x1, t1, TH1);
    tok_kernel<<<tokGrid, tokBlk>>>(x2, t2, TH2);

    dim3 gGrid(NC/64, NM/128);              // (8, 49)
    dim3 aGrid((NT + 127)/128, NH, NB);     // (13, 8, 4)
    const float qs = 0.125f * LOG2E, one = 1.0f;

    for (int i = 0; i < 3; i++) {
        const __nv_bfloat16* wq1i = WH + (size_t)(0*3 + i)*N2;
        const __nv_bfloat16* wk1i = WH + (size_t)(1*3 + i)*N2;
        const __nv_bfloat16* wv1i = WH + (size_t)(2*3 + i)*N2;
        const __nv_bfloat16* wq2i = WH + (size_t)(3*3 + i)*N2;
        const __nv_bfloat16* wk2i = WH + (size_t)(4*3 + i)*N2;
        const __nv_bfloat16* wv2i = WH + (size_t)(5*3 + i)*N2;

        ln_kernel<<<NM, 128>>>(t1, ln1g + i*NC, ln1b + i*NC, LNH);
        gemm_bf<0><<<gGrid, 256, BF_SMEM>>>(LNH, wq1i, bq1 + i*NC, Q1, qs);
        gemm_bf<0><<<gGrid, 256, BF_SMEM>>>(TH2, wk1i, bk1 + i*NC, K1, one);
        gemm_bf<1><<<gGrid, 256, BF_SMEM>>>(TH2, wv1i, bv1 + i*NC, V1, one);
        ln_kernel<<<NM, 128>>>(t2, ln2g + i*NC, ln2b + i*NC, LNH);
        gemm_bf<0><<<gGrid, 256, BF_SMEM>>>(LNH, wq2i, bq2 + i*NC, Q2, qs);
        gemm_bf<0><<<gGrid, 256, BF_SMEM>>>(TH1, wk2i, bk2 + i*NC, K2, one);
        gemm_bf<1><<<gGrid, 256, BF_SMEM>>>(TH1, wv2i, bv2 + i*NC, V2, one);

        bool last = (i == 2);
        attn_bf<<<aGrid, 256, ATTN_SMEM>>>(Q1, K1, V1, t1,
                                           last ? nullptr : TH1, last ? t1f : nullptr);
        attn_bf<<<aGrid, 256, ATTN_SMEM>>>(Q2, K2, V2, t2,
                                           last ? nullptr : TH2, last ? t2f : nullptr);
    }

    gemm_out<<<gGrid, 256, OUT_SMEM>>>(t1f, wf,      o1b, out,                      bn1g, bn1b);
    gemm_out<<<gGrid, 256, OUT_SMEM>>>(t2f, wf + N2, o2b, out + (size_t)NB*NC*NT,   bn2g, bn2b);
}

// round 6
// speedup vs baseline: 8.6616x; 1.1368x over previous
#include <cuda_runtime.h>
#include <cuda_bf16.h>
#include <cuda_fp16.h>
#include <cstdint>

static constexpr int NB = 4, NT = 1568, NC = 512, NH = 8, DH = 64;
static constexpr int NM = NB * NT;   // 6272
static constexpr int N2 = NC * NC;   // 262144
static constexpr float LOG2E = 1.4426950408889634f;

// ---------------- scratch ---------------------------------------------------
__device__ float g_t1 [NB*NT*NC];
__device__ float g_t2 [NB*NT*NC];
__device__ float g_t1f[NB*NT*NC];          // tf32 mirror for out-head
__device__ float g_t2f[NB*NT*NC];
__device__ float g_th1[NB*NT*NC/2];        // bf16 mirror of t1
__device__ float g_th2[NB*NT*NC/2];
__device__ float g_ln1h[NB*NT*NC/2];       // bf16 LN outputs (per stream)
__device__ float g_ln2h[NB*NT*NC/2];
__device__ float g_q1h[NB*NT*NC/2];
__device__ float g_k1h[NB*NT*NC/2];
__device__ float g_v1h[NB*NT*NC/2];        // V^T f16: [b][c][tok]
__device__ float g_q2h[NB*NT*NC/2];
__device__ float g_k2h[NB*NT*NC/2];
__device__ float g_v2h[NB*NT*NC/2];
__device__ float g_wh [18*N2/2];           // bf16 proj weights
__device__ float g_wf [2*N2];              // tf32 out-head weights

// ---------------- helpers ---------------------------------------------------
__device__ __forceinline__ uint32_t f2tf(float f) {
    uint32_t u;
    asm("cvt.rna.tf32.f32 %0, %1;\n" : "=r"(u) : "f"(f));
    return u;
}
__device__ __forceinline__ float f2tff(float f) { return __uint_as_float(f2tf(f)); }

__device__ __forceinline__ void mma_bf16(float* c, const uint32_t* a, const uint32_t* b) {
    asm volatile(
        "mma.sync.aligned.m16n8k16.row.col.f32.bf16.bf16.f32 "
        "{%0,%1,%2,%3}, {%4,%5,%6,%7}, {%8,%9}, {%0,%1,%2,%3};\n"
        : "+f"(c[0]), "+f"(c[1]), "+f"(c[2]), "+f"(c[3])
        : "r"(a[0]), "r"(a[1]), "r"(a[2]), "r"(a[3]), "r"(b[0]), "r"(b[1]));
}
__device__ __forceinline__ void mma_f16(float* c, const uint32_t* a, const uint32_t* b) {
    asm volatile(
        "mma.sync.aligned.m16n8k16.row.col.f32.f16.f16.f32 "
        "{%0,%1,%2,%3}, {%4,%5,%6,%7}, {%8,%9}, {%0,%1,%2,%3};\n"
        : "+f"(c[0]), "+f"(c[1]), "+f"(c[2]), "+f"(c[3])
        : "r"(a[0]), "r"(a[1]), "r"(a[2]), "r"(a[3]), "r"(b[0]), "r"(b[1]));
}
__device__ __forceinline__ void mma_tf32(float* c, const uint32_t* a, const uint32_t* b) {
    asm volatile(
        "mma.sync.aligned.m16n8k8.row.col.f32.tf32.tf32.f32 "
        "{%0,%1,%2,%3}, {%4,%5,%6,%7}, {%8,%9}, {%0,%1,%2,%3};\n"
        : "+f"(c[0]), "+f"(c[1]), "+f"(c[2]), "+f"(c[3])
        : "r"(a[0]), "r"(a[1]), "r"(a[2]), "r"(a[3]), "r"(b[0]), "r"(b[1]));
}
__device__ __forceinline__ void ldsm4(uint32_t& r0, uint32_t& r1, uint32_t& r2, uint32_t& r3,
                                      uint32_t addr) {
    asm volatile("ldmatrix.sync.aligned.m8n8.x4.shared.b16 {%0,%1,%2,%3}, [%4];\n"
                 : "=r"(r0), "=r"(r1), "=r"(r2), "=r"(r3) : "r"(addr));
}
// f16x2 {lo=exp2(lo_in), hi=exp2(hi_in)}
__device__ __forceinline__ uint32_t ex2h2(float lo, float hi) {
    uint32_t h, d;
    asm("cvt.rn.f16x2.f32 %0, %1, %2;\n" : "=r"(h) : "f"(hi), "f"(lo));
    asm("ex2.approx.f16x2 %0, %1;\n" : "=r"(d) : "r"(h));
    return d;
}
__device__ __forceinline__ void cp16(uint32_t dst, const void* src) {
    asm volatile("cp.async.cg.shared.global [%0], [%1], 16;\n" :: "r"(dst), "l"(src));
}
__device__ __forceinline__ void cp16z(uint32_t dst, const void* src, int bytes) {
    asm volatile("cp.async.cg.shared.global [%0], [%1], 16, %2;\n" :: "r"(dst), "l"(src), "r"(bytes));
}
__device__ __forceinline__ void cp_commit() { asm volatile("cp.async.commit_group;\n"); }
__device__ __forceinline__ void cp_wait0()  { asm volatile("cp.async.wait_group 0;\n"); }

// swizzled 16B-chunk address: 8 chunks (128B) per logical row
__device__ __forceinline__ uint32_t swz(uint32_t base, int row, int c) {
    return base + (uint32_t)((row * 8 + (c ^ (row & 7))) << 4);
}

// ---------------- weight pre-conversion ------------------------------------
struct WPtrs { const float* p[8]; };
__global__ void wcvt_kernel(WPtrs w, __nv_bfloat16* __restrict__ dh, float* __restrict__ df) {
    int mat = blockIdx.y;               // 0..19
    const float* src;
    if (mat < 18) src = w.p[mat/3] + (size_t)(mat%3) * N2;
    else          src = w.p[6 + (mat - 18)];
    int i = (blockIdx.x * 256 + threadIdx.x) * 4;
    float4 v = *(const float4*)(src + i);
    if (mat < 18) {
        __nv_bfloat162* d = (__nv_bfloat162*)(dh + (size_t)mat * N2 + i);
        d[0] = __floats2bfloat162_rn(v.x, v.y);
        d[1] = __floats2bfloat162_rn(v.z, v.w);
    } else {
        float4 o;
        o.x = f2tff(v.x); o.y = f2tff(v.y); o.z = f2tff(v.z); o.w = f2tff(v.w);
        *(float4*)(df + (size_t)(mat - 18) * N2 + i) = o;
    }
}

// ---------------- tokenize (fp32 + bf16 mirror), both streams ---------------
__global__ void tok_kernel(const float* __restrict__ x1, float* __restrict__ t1o,
                           __nv_bfloat16* __restrict__ th1o,
                           const float* __restrict__ x2, float* __restrict__ t2o,
                           __nv_bfloat16* __restrict__ th2o) {
    __shared__ float tile[32][33];
    int z = blockIdx.z;                 // 0..7 : b*2 + stream
    int b = z >> 1, st = z & 1;
    const float* x = st ? x2 : x1;
    float* t = st ? t2o : t1o;
    __nv_bfloat16* th = st ? th2o : th1o;
    int n0 = blockIdx.x * 32, c0 = blockIdx.y * 32;
    int nx = n0 + threadIdx.x;
    #pragma unroll
    for (int i = 0; i < 32; i += 8) {
        int c = c0 + threadIdx.y + i;
        tile[threadIdx.y + i][threadIdx.x] = x[((size_t)b*NC + c)*NT + nx];
    }
    __syncthreads();
    int cx = c0 + threadIdx.x;
    #pragma unroll
    for (int i = 0; i < 32; i += 8) {
        int n = n0 + threadIdx.y + i;
        float v = tile[threadIdx.x][threadIdx.y + i];
        size_t off = ((size_t)b*NT + n)*NC + cx;
        t[off]  = v;
        th[off] = __float2bfloat16_rn(v);
    }
}

// ---------------- LayerNorm (both streams, fp32 in, bf16 out) ---------------
__global__ void ln_kernel(const float* __restrict__ tA, const float* __restrict__ gA,
                          const float* __restrict__ bA, __nv_bfloat16* __restrict__ oA,
                          const float* __restrict__ tB, const float* __restrict__ gB,
                          const float* __restrict__ bB, __nv_bfloat16* __restrict__ oB) {
    int row = blockIdx.x;
    const float* t = blockIdx.y ? tB : tA;
    const float* gamma = blockIdx.y ? gB : gA;
    const float* beta  = blockIdx.y ? bB : bA;
    __nv_bfloat16* out = blockIdx.y ? oB : oA;
    int tid = threadIdx.x; // 128
    const float4* x4 = (const float4*)(t + (size_t)row * NC);
    float4 v = x4[tid];
    float s  = v.x + v.y + v.z + v.w;
    float s2 = v.x*v.x + v.y*v.y + v.z*v.z + v.w*v.w;
    #pragma unroll
    for (int o = 16; o > 0; o >>= 1) {
        s  += __shfl_xor_sync(0xffffffffu, s,  o);
        s2 += __shfl_xor_sync(0xffffffffu, s2, o);
    }
    __shared__ float ss[4], ss2[4];
    int w = tid >> 5;
    if ((tid & 31) == 0) { ss[w] = s; ss2[w] = s2; }
    __syncthreads();
    s  = ss[0] + ss[1] + ss[2] + ss[3];
    s2 = ss2[0] + ss2[1] + ss2[2] + ss2[3];
    float mean = s * (1.0f / NC);
    float var  = s2 * (1.0f / NC) - mean * mean;
    float rstd = rsqrtf(var + 1e-5f);
    float4 g4 = ((const float4*)gamma)[tid];
    float4 b4 = ((const float4*)beta)[tid];
    __nv_bfloat162* o2 = (__nv_bfloat162*)(out + (size_t)row * NC);
    o2[tid*2    ] = __floats2bfloat162_rn((v.x - mean)*rstd*g4.x + b4.x,
                                          (v.y - mean)*rstd*g4.y + b4.y);
    o2[tid*2 + 1] = __floats2bfloat162_rn((v.z - mean)*rstd*g4.z + b4.z,
                                          (v.w - mean)*rstd*g4.w + b4.w);
}

// ---------------- merged bf16 proj GEMM (6 ops per launch) ------------------
// op.mode 0: Y bf16 row-major, (acc+bias)*scale
// op.mode 1: Y half, V^T store [b][c][tok], acc+bias
struct PArg {
    const __nv_bfloat16 *A, *W;
    const float *bias;
    void *Y;
    float scale;
    int mode;
};
struct PArgs { PArg op[6]; };

__global__ __launch_bounds__(256, 2)
void gemm_proj(PArgs pa) {
    constexpr int BM = 128, BN = 128, BK = 64;
    const PArg p = pa.op[blockIdx.z];
    extern __shared__ char smc[];
    const uint32_t sb = (uint32_t)__cvta_generic_to_shared(smc);
    const int tid = threadIdx.x, lane = tid & 31, warp = tid >> 5;
    const int g = lane >> 2, tg = lane & 3;
    const int wm = warp >> 2, wn = warp & 3;      // 2 x 4 warp grid
    const int m0 = blockIdx.y * BM, n0 = blockIdx.x * BN;
    const __nv_bfloat16* X = p.A;
    const __nv_bfloat16* W = p.W;

    float acc[4][4][4] = {};

    auto issue = [&](int st, int k0) {
        uint32_t aB = sb + (uint32_t)st * 16384u;
        uint32_t bB = sb + 32768u + (uint32_t)st * 16384u;
        #pragma unroll
        for (int i = 0; i < 4; i++) {
            int idx = tid + i*256;               // 0..1023
            int r = idx >> 3, c = idx & 7;
            cp16(swz(aB, r, c), X + (size_t)(m0 + r)*NC + k0 + c*8);
        }
        #pragma unroll
        for (int i = 0; i < 4; i++) {
            int idx = tid + i*256;
            int r = idx >> 3, c = idx & 7;
            cp16(swz(bB, r, c), W + (size_t)(n0 + r)*NC + k0 + c*8);
        }
        cp_commit();
    };

    issue(0, 0);
    #pragma unroll 1
    for (int it = 0; it < NC/BK; ++it) {         // 8 iters
        cp_wait0();
        __syncthreads();
        if (it + 1 < NC/BK) issue((it + 1) & 1, (it + 1)*BK);
        uint32_t aB = sb + (uint32_t)(it & 1) * 16384u;
        uint32_t bB = sb + 32768u + (uint32_t)(it & 1) * 16384u;
        #pragma unroll
        for (int j = 0; j < 4; j++) {            // k16 chunks
            uint32_t a[4][4], bf[4][2];
            #pragma unroll
            for (int mt = 0; mt < 4; mt++) {
                int row = wm*64 + mt*16 + (lane & 15);
                int c   = 2*j + (lane >> 4);
                ldsm4(a[mt][0], a[mt][1], a[mt][2], a[mt][3], swz(aB, row, c));
            }
            #pragma unroll
            for (int q = 0; q < 2; q++) {
                int row = wn*32 + q*16 + ((lane >> 4) << 3) + (lane & 7);
                int c   = 2*j + ((lane >> 3) & 1);
                uint32_t r0, r1, r2, r3;
                ldsm4(r0, r1, r2, r3, swz(bB, row, c));
                bf[q*2][0] = r0; bf[q*2][1] = r1;
                bf[q*2+1][0] = r2; bf[q*2+1][1] = r3;
            }
            #pragma unroll
            for (int mt = 0; mt < 4; mt++)
                #pragma unroll
                for (int nt = 0; nt < 4; nt++)
                    mma_bf16(acc[mt][nt], a[mt], bf[nt]);
        }
    }

    if (p.mode == 0) {
        __nv_bfloat16* Y = (__nv_bfloat16*)p.Y;
        float scale = p.scale;
        #pragma unroll
        for (int mt = 0; mt < 4; mt++) {
            #pragma unroll
            for (int nt = 0; nt < 4; nt++) {
                int r0 = m0 + wm*64 + mt*16 + g;
                int c0 = n0 + wn*32 + nt*8 + 2*tg;
                float b0 = p.bias[c0], b1 = p.bias[c0 + 1];
                *(__nv_bfloat162*)(Y + (size_t)r0*NC + c0) =
                    __floats2bfloat162_rn((acc[mt][nt][0] + b0)*scale, (acc[mt][nt][1] + b1)*scale);
                *(__nv_bfloat162*)(Y + (size_t)(r0+8)*NC + c0) =
                    __floats2bfloat162_rn((acc[mt][nt][2] + b0)*scale, (acc[mt][nt][3] + b1)*scale);
            }
        }
    } else {
        __half* Y = (__half*)p.Y;
        #pragma unroll
        for (int mt = 0; mt < 4; mt++) {
            #pragma unroll
            for (int nt = 0; nt < 4; nt++) {
                int r0 = m0 + wm*64 + mt*16 + g;
                int c0 = n0 + wn*32 + nt*8 + 2*tg;
                #pragma unroll
                for (int e = 0; e < 4; e++) {
                    int r = r0 + (e >> 1)*8;
                    int o = c0 + (e & 1);
                    int b = r / NT, n = r % NT;
                    Y[((size_t)b*NC + o)*NT + n] = __float2half_rn(acc[mt][nt][e] + p.bias[o]);
                }
            }
        }
    }
}

// ---------------- FlashAttention-2, both streams, f16 exp/PV ----------------
struct AArgs {
    const __nv_bfloat16 *Q[2], *K[2];
    const __half *Vt[2];
    float *T[2];
    __nv_bfloat16 *Th[2];
    float *Tf[2];
};

__global__ __launch_bounds__(256, 2)
void attn_bf(AArgs aa) {
    extern __shared__ char smc[];
    const uint32_t sb  = (uint32_t)__cvta_generic_to_shared(smc);
    const uint32_t sbQ = sb;
    const int z = blockIdx.z;
    const int b = z >> 1, st = z & 1;
    const __nv_bfloat16* Q = aa.Q[st];
    const __nv_bfloat16* K = aa.K[st];
    const __half*       Vt = aa.Vt[st];
    float* T = aa.T[st];
    __nv_bfloat16* Th = aa.Th[st];
    float* Tf = aa.Tf[st];

    const int q0 = blockIdx.x * 128;
    const int h  = blockIdx.y;
    const int tid = threadIdx.x;
    const int lane = tid & 31, warp = tid >> 5;
    const int g = lane >> 2, tg = lane & 3;
    const int wr = warp * 16;
    const size_t base  = ((size_t)b * NT) * NC + h * DH;
    const size_t vbase = ((size_t)b * NC + h * DH) * NT;

    #pragma unroll
    for (int i = 0; i < 4; i++) {
        int idx = tid + i*256;
        int r = idx >> 3, c = idx & 7;
        int row = q0 + r;
        int ok = (row < NT) ? 16 : 0;
        if (row >= NT) row = NT - 1;
        cp16z(swz(sbQ, r, c), Q + base + (size_t)row*NC + c*8, ok);
    }
    auto issueKV = [&](int stg, int kt) {
        uint32_t kB = sb + 16384u + (uint32_t)stg*8192u;
        uint32_t vB = sb + 32768u + (uint32_t)stg*8192u;
        #pragma unroll
        for (int i = 0; i < 2; i++) {
            int idx = tid + i*256;
            int r = idx >> 3, c = idx & 7;
            int krow = kt + r;
            int kok = (krow < NT) ? 16 : 0;
            if (krow >= NT) krow = NT - 1;
            cp16z(swz(kB, r, c), K + base + (size_t)krow*NC + c*8, kok);
            int vtok = kt + c*8;
            int vok = (vtok < NT) ? 16 : 0;
            if (vtok >= NT) vtok = NT - 8;
            cp16z(swz(vB, r, c), Vt + vbase + (size_t)r*NT + vtok, vok);
        }
        cp_commit();
    };
    issueKV(0, 0);

    uint32_t qf[4][4];
    float o[8][4] = {};
    float mrow0 = -1e30f, mrow1 = -1e30f, lrow0 = 0.0f, lrow1 = 0.0f;
    constexpr int NIT = (NT + 63) / 64;            // 25

    #pragma unroll 1
    for (int it = 0; it < NIT; ++it) {
        cp_wait0();
        __syncthreads();
        if (it == 0) {
            #pragma unroll
            for (int j = 0; j < 4; j++) {
                int row = wr + (lane & 15);
                int c   = 2*j + (lane >> 4);
                ldsm4(qf[j][0], qf[j][1], qf[j][2], qf[j][3], swz(sbQ, row, c));
            }
        }
        if (it + 1 < NIT) issueKV((it + 1) & 1, (it + 1)*64);

        const uint32_t kB = sb + 16384u + (uint32_t)((it & 1))*8192u;
        const uint32_t vB = sb + 32768u + (uint32_t)((it & 1))*8192u;
        const int kt = it * 64;

        // ---- S = Q K^T (bf16)
        float s[8][4] = {};
        #pragma unroll
        for (int j = 0; j < 4; j++) {
            #pragma unroll
            for (int q = 0; q < 4; q++) {
                int row = q*16 + ((lane >> 4) << 3) + (lane & 7);
                int c   = 2*j + ((lane >> 3) & 1);
                uint32_t r0, r1, r2, r3;
                ldsm4(r0, r1, r2, r3, swz(kB, row, c));
                uint32_t f0[2] = {r0, r1}, f1[2] = {r2, r3};
                mma_bf16(s[q*2    ], qf[j], f0);
                mma_bf16(s[q*2 + 1], qf[j], f1);
            }
        }

        if (kt + 64 > NT) {
            #pragma unroll
            for (int nt = 0; nt < 8; nt++) {
                int c0 = kt + nt*8 + 2*tg;
                if (c0     >= NT) { s[nt][0] = -1e30f; s[nt][2] = -1e30f; }
                if (c0 + 1 >= NT) { s[nt][1] = -1e30f; s[nt][3] = -1e30f; }
            }
        }

        // ---- online softmax (rows g, g+8), base-2, f16x2 exponentials
        float mx0 = -1e30f, mx1 = -1e30f;
        #pragma unroll
        for (int nt = 0; nt < 8; nt++) {
            mx0 = fmaxf(mx0, fmaxf(s[nt][0], s[nt][1]));
            mx1 = fmaxf(mx1, fmaxf(s[nt][2], s[nt][3]));
        }
        mx0 = fmaxf(mx0, __shfl_xor_sync(0xffffffffu, mx0, 1));
        mx0 = fmaxf(mx0, __shfl_xor_sync(0xffffffffu, mx0, 2));
        mx1 = fmaxf(mx1, __shfl_xor_sync(0xffffffffu, mx1, 1));
        mx1 = fmaxf(mx1, __shfl_xor_sync(0xffffffffu, mx1, 2));
        float mn0 = fmaxf(mrow0, mx0), mn1 = fmaxf(mrow1, mx1);
        float cr0 = exp2f(mrow0 - mn0), cr1 = exp2f(mrow1 - mn1);
        mrow0 = mn0; mrow1 = mn1;

        uint32_t pa[4][4];
        __half2 sh0 = __floats2half2_rn(0.0f, 0.0f);
        __half2 sh1 = __floats2half2_rn(0.0f, 0.0f);
        #pragma unroll
        for (int j = 0; j < 4; j++) {
            uint32_t a0 = ex2h2(s[2*j][0]   - mn0, s[2*j][1]   - mn0);
            uint32_t a1 = ex2h2(s[2*j][2]   - mn1, s[2*j][3]   - mn1);
            uint32_t a2 = ex2h2(s[2*j+1][0] - mn0, s[2*j+1][1] - mn0);
            uint32_t a3 = ex2h2(s[2*j+1][2] - mn1, s[2*j+1][3] - mn1);
            pa[j][0] = a0; pa[j][1] = a1; pa[j][2] = a2; pa[j][3] = a3;
            sh0 = __hadd2(sh0, __hadd2(*(__half2*)&a0, *(__half2*)&a2));
            sh1 = __hadd2(sh1, __hadd2(*(__half2*)&a1, *(__half2*)&a3));
        }
        float2 f0 = __half22float2(sh0);
        float2 f1 = __half22float2(sh1);
        float sum0 = f0.x + f0.y, sum1 = f1.x + f1.y;
        sum0 += __shfl_xor_sync(0xffffffffu, sum0, 1);
        sum0 += __shfl_xor_sync(0xffffffffu, sum0, 2);
        sum1 += __shfl_xor_sync(0xffffffffu, sum1, 1);
        sum1 += __shfl_xor_sync(0xffffffffu, sum1, 2);
        lrow0 = lrow0 * cr0 + sum0;
        lrow1 = lrow1 * cr1 + sum1;

        #pragma unroll
        for (int nt = 0; nt < 8; nt++) {
            o[nt][0] *= cr0; o[nt][1] *= cr0;
            o[nt][2] *= cr1; o[nt][3] *= cr1;
        }

        // ---- O += P V (f16 mma; P frags straight from ex2 output)
        #pragma unroll
        for (int j = 0; j < 4; j++) {
            #pragma unroll
            for (int q = 0; q < 4; q++) {
                int row = q*16 + ((lane >> 4) << 3) + (lane & 7);   // dim
                int c   = 2*j + ((lane >> 3) & 1);                  // token chunk
                uint32_t r0, r1, r2, r3;
                ldsm4(r0, r1, r2, r3, swz(vB, row, c));
                uint32_t f0v[2] = {r0, r1}, f1v[2] = {r2, r3};
                mma_f16(o[q*2    ], pa[j], f0v);
                mma_f16(o[q*2 + 1], pa[j], f1v);
            }
        }
    }

    // epilogue: T += O/l ; optional mirrors
    int r0 = q0 + wr + g, r1 = r0 + 8;
    float inv0 = 1.0f / lrow0, inv1 = 1.0f / lrow1;
    #pragma unroll
    for (int nt = 0; nt < 8; nt++) {
        int d = nt*8 + 2*tg;
        if (r0 < NT) {
            size_t off = base + (size_t)r0*NC + d;
            float n0 = T[off]     + o[nt][0] * inv0;
            float n1 = T[off + 1] + o[nt][1] * inv0;
            T[off] = n0;  T[off + 1] = n1;
            if (Th) *(__nv_bfloat162*)(Th + off) = __floats2bfloat162_rn(n0, n1);
            if (Tf) { Tf[off] = f2tff(n0); Tf[off + 1] = f2tff(n1); }
        }
        if (r1 < NT) {
            size_t off = base + (size_t)r1*NC + d;
            float n0 = T[off]     + o[nt][2] * inv1;
            float n1 = T[off + 1] + o[nt][3] * inv1;
            T[off] = n0;  T[off + 1] = n1;
            if (Th) *(__nv_bfloat162*)(Th + off) = __floats2bfloat162_rn(n0, n1);
            if (Tf) { Tf[off] = f2tff(n0); Tf[off + 1] = f2tff(n1); }
        }
    }
}

// ---------------- TF32 out-head GEMM (both heads, relu/bn, transposed) ------
struct OArg { const float *X, *W, *bias, *bng, *bnb; float *Y; };
struct OArgs { OArg op[2]; };

__global__ __launch_bounds__(256)
void gemm_out(OArgs oa) {
    constexpr int BM = 128, BN = 64, BK = 32;
    const OArg p = oa.op[blockIdx.z];
    extern __shared__ float smem[];
    const uint32_t sb = (uint32_t)__cvta_generic_to_shared(smem);
    const int tid = threadIdx.x, lane = tid & 31, warp = tid >> 5;
    const int g = lane >> 2, tg = lane & 3;
    const int wm = warp >> 1, wn = warp & 1;
    const int m0 = blockIdx.y * BM, n0 = blockIdx.x * BN;
    const float* X = p.X;
    const float* W = p.W;

    float acc[2][4][4] = {};

    auto issue = [&](int st, int k0) {
        uint32_t aB = sb + (uint32_t)(st*BM*BK)*4u;
        uint32_t bB = sb + (uint32_t)(2*BM*BK + st*BN*BK)*4u;
        #pragma unroll
        for (int i = 0; i < 4; i++) {
            int idx = tid + i*256;
            int r = idx >> 3, c4 = idx & 7;
            cp16(aB + 4u*(r*32 + ((c4 ^ (r & 7)) << 2)),
                 X + (size_t)(m0 + r)*NC + k0 + c4*4);
        }
        #pragma unroll
        for (int i = 0; i < 2; i++) {
            int idx = tid + i*256;
            int r = idx >> 3, c4 = idx & 7;
            cp16(bB + 4u*(r*32 + ((c4 ^ (r & 7)) << 2)),
                 W + (size_t)(n0 + r)*NC + k0 + c4*4);
        }
        cp_commit();
    };

    issue(0, 0);
    #pragma unroll 1
    for (int it = 0; it < NC/BK; ++it) {
        cp_wait0();
        __syncthreads();
        if (it + 1 < NC/BK) issue((it + 1) & 1, (it + 1)*BK);
        const uint32_t aBase = sb + (uint32_t)((it & 1)*BM*BK)*4u;
        const uint32_t bBase = sb + (uint32_t)(2*BM*BK + (it & 1)*BN*BK)*4u;
        #pragma unroll
        for (int kk = 0; kk < BK; kk += 8) {
            const int c0 = kk >> 2;
            uint32_t a[2][4], b[4][2];
            #pragma unroll
            for (int mt = 0; mt < 2; mt++) {
                int row = wm*32 + mt*16 + (lane & 15);
                int c4  = c0 + (lane >> 4);
                ldsm4(a[mt][0], a[mt][1], a[mt][2], a[mt][3],
                      aBase + 4u*(row*32 + ((c4 ^ (row & 7)) << 2)));
            }
            #pragma unroll
            for (int pq = 0; pq < 2; pq++) {
                int row = wn*32 + ((pq*2 + ((lane >> 4) & 1)) << 3) + (lane & 7);
                int c4  = c0 + ((lane >> 3) & 1);
                ldsm4(b[pq*2][0], b[pq*2][1], b[pq*2+1][0], b[pq*2+1][1],
                      bBase + 4u*(row*32 + ((c4 ^ (row & 7)) << 2)));
            }
            #pragma unroll
            for (int mt = 0; mt < 2; mt++)
                #pragma unroll
                for (int nt = 0; nt < 4; nt++)
                    mma_tf32(acc[mt][nt], a[mt], b[nt]);
        }
    }

    const float bns = rsqrtf(1.0f + 1e-5f);
    #pragma unroll
    for (int mt = 0; mt < 2; mt++) {
        #pragma unroll
        for (int nt = 0; nt < 4; nt++) {
            int r0 = m0 + wm*32 + mt*16 + g;
            int c0 = n0 + wn*32 + nt*8 + 2*tg;
            #pragma unroll
            for (int e = 0; e < 4; e++) {
                int r = r0 + (e >> 1)*8;
                int oc = c0 + (e & 1);
                int b = r / NT, n = r % NT;
                float z = acc[mt][nt][e] + p.bias[oc];
                z = fmaxf(z, 0.0f) * bns;
                p.Y[((size_t)b*NC + oc)*NT + n] = z * p.bng[oc] + p.bnb[oc];
            }
        }
    }
}

// ---------------------------------------------------------------------------
extern "C" void kernel_launch(void* const* d_in, const int* in_sizes, int n_in,
                              void* d_out, int out_size) {
    const float* x1   = (const float*)d_in[0];
    const float* x2   = (const float*)d_in[1];
    const float* Wq1  = (const float*)d_in[2];
    const float* bq1  = (const float*)d_in[3];
    const float* Wk1  = (const float*)d_in[4];
    const float* bk1  = (const float*)d_in[5];
    const float* Wv1  = (const float*)d_in[6];
    const float* bv1  = (const float*)d_in[7];
    const float* ln1g = (const float*)d_in[8];
    const float* ln1b = (const float*)d_in[9];
    const float* Wq2  = (const float*)d_in[10];
    const float* bq2  = (const float*)d_in[11];
    const float* Wk2  = (const float*)d_in[12];
    const float* bk2  = (const float*)d_in[13];
    const float* Wv2  = (const float*)d_in[14];
    const float* bv2  = (const float*)d_in[15];
    const float* ln2g = (const float*)d_in[16];
    const float* ln2b = (const float*)d_in[17];
    const float* o1w  = (const float*)d_in[18];
    const float* o1b  = (const float*)d_in[19];
    const float* bn1g = (const float*)d_in[20];
    const float* bn1b = (const float*)d_in[21];
    const float* o2w  = (const float*)d_in[22];
    const float* o2b  = (const float*)d_in[23];
    const float* bn2g = (const float*)d_in[24];
    const float* bn2b = (const float*)d_in[25];
    float* out = (float*)d_out;

    float *t1, *t2, *t1f, *t2f, *wf;
    void *th1, *th2, *ln1h, *ln2h, *q1h, *k1h, *v1h, *q2h, *k2h, *v2h, *wh;
    cudaGetSymbolAddress((void**)&t1,  g_t1);
    cudaGetSymbolAddress((void**)&t2,  g_t2);
    cudaGetSymbolAddress((void**)&t1f, g_t1f);
    cudaGetSymbolAddress((void**)&t2f, g_t2f);
    cudaGetSymbolAddress(&th1,  g_th1);
    cudaGetSymbolAddress(&th2,  g_th2);
    cudaGetSymbolAddress(&ln1h, g_ln1h);
    cudaGetSymbolAddress(&ln2h, g_ln2h);
    cudaGetSymbolAddress(&q1h, g_q1h);
    cudaGetSymbolAddress(&k1h, g_k1h);
    cudaGetSymbolAddress(&v1h, g_v1h);
    cudaGetSymbolAddress(&q2h, g_q2h);
    cudaGetSymbolAddress(&k2h, g_k2h);
    cudaGetSymbolAddress(&v2h, g_v2h);
    cudaGetSymbolAddress(&wh,  g_wh);
    cudaGetSymbolAddress((void**)&wf, g_wf);
    __nv_bfloat16 *TH1 = (__nv_bfloat16*)th1, *TH2 = (__nv_bfloat16*)th2;
    __nv_bfloat16 *LN1 = (__nv_bfloat16*)ln1h, *LN2 = (__nv_bfloat16*)ln2h;
    __nv_bfloat16 *WH = (__nv_bfloat16*)wh;
    __nv_bfloat16 *Q1 = (__nv_bfloat16*)q1h, *K1 = (__nv_bfloat16*)k1h;
    __nv_bfloat16 *Q2 = (__nv_bfloat16*)q2h, *K2 = (__nv_bfloat16*)k2h;
    __half *V1 = (__half*)v1h, *V2 = (__half*)v2h;

    const int PROJ_SMEM = 65536;
    const int OUT_SMEM  = 49152;
    const int ATTN_SMEM = 49152;
    cudaFuncSetAttribute(gemm_proj, cudaFuncAttributeMaxDynamicSharedMemorySize, PROJ_SMEM);
    cudaFuncSetAttribute(gemm_out,  cudaFuncAttributeMaxDynamicSharedMemorySize, OUT_SMEM);
    cudaFuncSetAttribute(attn_bf,   cudaFuncAttributeMaxDynamicSharedMemorySize, ATTN_SMEM);

    WPtrs wp;
    wp.p[0] = Wq1; wp.p[1] = Wk1; wp.p[2] = Wv1;
    wp.p[3] = Wq2; wp.p[4] = Wk2; wp.p[5] = Wv2;
    wp.p[6] = o1w; wp.p[7] = o2w;
    wcvt_kernel<<<dim3(N2/1024, 20), 256>>>(wp, WH, wf);

    dim3 tokGrid(NT/32, NC/32, 2*NB), tokBlk(32, 8);
    tok_kernel<<<tokGrid, tokBlk>>>(x1, t1, TH1, x2, t2, TH2);

    dim3 pGrid(NC/128, NM/128, 6);          // (4, 49, 6)
    dim3 aGrid((NT + 127)/128, NH, 2*NB);   // (13, 8, 8)
    dim3 oGrid(NC/64, NM/128, 2);           // (8, 49, 2)
    const float qs = 0.125f * LOG2E, one = 1.0f;

    for (int i = 0; i < 3; i++) {
        ln_kernel<<<dim3(NM, 2), 128>>>(t1, ln1g + i*NC, ln1b + i*NC, LN1,
                                        t2, ln2g + i*NC, ln2b + i*NC, LN2);
        PArgs pa;
        pa.op[0] = { LN1, WH + (size_t)(0*3 + i)*N2, bq1 + i*NC, Q1, qs,  0 };
        pa.op[1] = { TH2, WH + (size_t)(1*3 + i)*N2, bk1 + i*NC, K1, one, 0 };
        pa.op[2] = { TH2, WH + (size_t)(2*3 + i)*N2, bv1 + i*NC, V1, one, 1 };
        pa.op[3] = { LN2, WH + (size_t)(3*3 + i)*N2, bq2 + i*NC, Q2, qs,  0 };
        pa.op[4] = { TH1, WH + (size_t)(4*3 + i)*N2, bk2 + i*NC, K2, one, 0 };
        pa.op[5] = { TH1, WH + (size_t)(5*3 + i)*N2, bv2 + i*NC, V2, one, 1 };
        gemm_proj<<<pGrid, 256, PROJ_SMEM>>>(pa);

        bool last = (i == 2);
        AArgs aa;
        aa.Q[0] = Q1;  aa.Q[1] = Q2;
        aa.K[0] = K1;  aa.K[1] = K2;
        aa.Vt[0] = V1; aa.Vt[1] = V2;
        aa.T[0] = t1;  aa.T[1] = t2;
        aa.Th[0] = last ? nullptr : TH1;  aa.Th[1] = last ? nullptr : TH2;
        aa.Tf[0] = last ? t1f : nullptr;  aa.Tf[1] = last ? t2f : nullptr;
        attn_bf<<<aGrid, 256, ATTN_SMEM>>>(aa);
    }

    OArgs oa;
    oa.op[0] = { t1f, wf,      o1b, bn1g, bn1b, out };
    oa.op[1] = { t2f, wf + N2, o2b, bn2g, bn2b, out + (size_t)NB*NC*NT };
    gemm_out<<<oGrid, 256, OUT_SMEM>>>(oa);
}